// round 1
// baseline (speedup 1.0000x reference)
#include <cuda_runtime.h>
#include <math.h>

// ---------------- problem constants ----------------
#define NB 2
#define NS 1024
#define ND 1024
#define NH 16
#define NDH 64
#define NL 4
#define NDFF 4096
#define NV 32000
#define NR 2047              // 2*MAXLEN-1
#define NROWS (NB*NS)        // 2048

// ---------------- scratch (static device allocations) ----------------
__device__ float g_x[NROWS*ND];
__device__ float g_q[NROWS*ND];
__device__ float g_k[NROWS*ND];
__device__ float g_v[NROWS*ND];
__device__ float g_o[NROWS*ND];
__device__ float g_t[NROWS*ND];
__device__ float g_h[NROWS*NDFF];
__device__ float g_qr[(size_t)NROWS*NH*NR];   // [B*S*H, 2047]

// ---------------- embedding: x = emb[tgt] * sqrt(D) ----------------
__global__ void embed_kernel(const int* __restrict__ tgt,
                             const float* __restrict__ emb,
                             float* __restrict__ x) {
    int idx = blockIdx.x * blockDim.x + threadIdx.x;  // over NROWS*ND/4
    int row = idx >> 8;                               // ND/4 = 256 float4 per row
    int c4  = idx & 255;
    float4 v = reinterpret_cast<const float4*>(emb + (size_t)tgt[row] * ND)[c4];
    v.x *= 32.f; v.y *= 32.f; v.z *= 32.f; v.w *= 32.f;
    reinterpret_cast<float4*>(x)[idx] = v;
}

// ---------------- generic SGEMM: C[M,N] = alpha*(A[M,K] @ B[N,K]^T + bias) ----------------
#define BM 128
#define BN 128
#define BKK 16

__global__ __launch_bounds__(256) void gemm_nt(
    float* __restrict__ C, const float* __restrict__ A, const float* __restrict__ Bm,
    const float* __restrict__ bias, int M, int N, int K, float alpha, int relu)
{
    __shared__ float As[BKK][BM+4];
    __shared__ float Bs[BKK][BN+4];
    int tid = threadIdx.x;
    int m0 = blockIdx.y * BM;
    int n0 = blockIdx.x * BN;
    int tx = tid & 15, ty = tid >> 4;
    int lr = tid >> 2;           // 0..63
    int lc = (tid & 3) << 2;     // 0,4,8,12

    float acc[8][8];
    #pragma unroll
    for (int i = 0; i < 8; i++)
        #pragma unroll
        for (int j = 0; j < 8; j++) acc[i][j] = 0.f;

    for (int k0 = 0; k0 < K; k0 += BKK) {
        #pragma unroll
        for (int hh = 0; hh < 2; hh++) {
            int r  = lr + hh*64;
            int gm = m0 + r;
            float4 va = make_float4(0.f,0.f,0.f,0.f);
            if (gm < M) va = *reinterpret_cast<const float4*>(&A[(size_t)gm*K + k0 + lc]);
            As[lc+0][r] = va.x; As[lc+1][r] = va.y; As[lc+2][r] = va.z; As[lc+3][r] = va.w;
            int gn = n0 + r;
            float4 vb = make_float4(0.f,0.f,0.f,0.f);
            if (gn < N) vb = *reinterpret_cast<const float4*>(&Bm[(size_t)gn*K + k0 + lc]);
            Bs[lc+0][r] = vb.x; Bs[lc+1][r] = vb.y; Bs[lc+2][r] = vb.z; Bs[lc+3][r] = vb.w;
        }
        __syncthreads();
        #pragma unroll
        for (int kk = 0; kk < BKK; kk++) {
            float a[8], b[8];
            *(float4*)&a[0] = *(const float4*)&As[kk][ty*4];
            *(float4*)&a[4] = *(const float4*)&As[kk][64 + ty*4];
            *(float4*)&b[0] = *(const float4*)&Bs[kk][tx*4];
            *(float4*)&b[4] = *(const float4*)&Bs[kk][64 + tx*4];
            #pragma unroll
            for (int ii = 0; ii < 8; ii++)
                #pragma unroll
                for (int jj = 0; jj < 8; jj++)
                    acc[ii][jj] += a[ii]*b[jj];
        }
        __syncthreads();
    }

    #pragma unroll
    for (int ii = 0; ii < 8; ii++) {
        int gm = m0 + (ii < 4 ? ty*4 + ii : 64 + ty*4 + ii - 4);
        if (gm >= M) continue;
        #pragma unroll
        for (int jj = 0; jj < 8; jj++) {
            int gn = n0 + (jj < 4 ? tx*4 + jj : 64 + tx*4 + jj - 4);
            if (gn >= N) continue;
            float vv = acc[ii][jj];
            if (bias) vv += bias[gn];
            vv *= alpha;
            if (relu) vv = fmaxf(vv, 0.f);
            C[(size_t)gm*N + gn] = vv;
        }
    }
}

// ---------------- fused attention (flash-style, exact softmax semantics) ----------------
// grid: (S/128, H, B), 128 threads; each thread owns one query row.
// Processes ALL key tiles (masked values are exactly -1e9, matching the reference
// including the degenerate all-masked-row case).
#define QT 128
#define KT 64
#define LDQ 68   // padded row stride (float4-aligned, conflict-free)

__global__ __launch_bounds__(128) void attn_kernel(
    float* __restrict__ out, const float* __restrict__ q, const float* __restrict__ k,
    const float* __restrict__ v, const float* __restrict__ qr, const int* __restrict__ tgt)
{
    extern __shared__ float sm[];
    float* qs = sm;                       // [128][68]
    float* ks = qs + QT*LDQ;              // [64][68]
    float* vs = ks + KT*LDQ;              // [64][68]
    float* ps = vs + KT*LDQ;              // [128][68]
    int*   pf = (int*)(ps + QT*LDQ);      // [64]

    int b = blockIdx.z, h = blockIdx.y;
    int tid = threadIdx.x;
    int i0 = blockIdx.x * QT;
    int i  = i0 + tid;

    // load Q tile (vectorized, coalesced)
    for (int t = tid; t < QT*NDH/4; t += 128) {
        int r  = t >> 4;          // NDH/4 = 16 float4 per row
        int c4 = (t & 15) << 2;
        float4 va = *reinterpret_cast<const float4*>(
            &q[((size_t)(b*NS + i0 + r))*ND + h*NDH + c4]);
        *reinterpret_cast<float4*>(&qs[r*LDQ + c4]) = va;
    }

    float o[NDH];
    #pragma unroll
    for (int d = 0; d < NDH; d++) o[d] = 0.f;
    float m = -1e30f, l = 0.f;
    const float* qrrow = qr + ((size_t)((b*NS + i)*NH + h)) * NR + (1023 - i);

    for (int j0 = 0; j0 < NS; j0 += KT) {
        __syncthreads();
        for (int t = tid; t < KT*NDH/4; t += 128) {
            int r  = t >> 4;
            int c4 = (t & 15) << 2;
            size_t g = ((size_t)(b*NS + j0 + r))*ND + h*NDH + c4;
            *reinterpret_cast<float4*>(&ks[r*LDQ + c4]) =
                *reinterpret_cast<const float4*>(&k[g]);
            *reinterpret_cast<float4*>(&vs[r*LDQ + c4]) =
                *reinterpret_cast<const float4*>(&v[g]);
        }
        if (tid < KT) pf[tid] = (tgt[b*NS + j0 + tid] == 0) ? 1 : 0;
        __syncthreads();

        // s_j = q_i . k_j
        float s[KT];
        #pragma unroll
        for (int j = 0; j < KT; j++) s[j] = 0.f;
        #pragma unroll 1
        for (int d = 0; d < NDH; d += 4) {
            float4 qd = *reinterpret_cast<const float4*>(&qs[tid*LDQ + d]);
            #pragma unroll
            for (int j = 0; j < KT; j++) {
                float4 kj = *reinterpret_cast<const float4*>(&ks[j*LDQ + d]);
                s[j] += qd.x*kj.x + qd.y*kj.y + qd.z*kj.z + qd.w*kj.w;
            }
        }
        // + relative term, masks, running max
        float mt = m;
        #pragma unroll
        for (int j = 0; j < KT; j++) {
            int jj = j0 + j;
            float val = s[j] + qrrow[jj];
            if (jj > i || pf[j]) val = -1e9f;
            s[j] = val;
            mt = fmaxf(mt, val);
        }
        float corr = __expf(m - mt);
        m = mt;
        l *= corr;
        #pragma unroll
        for (int d = 0; d < NDH; d++) o[d] *= corr;
        // p = exp(s - m), stash per-thread row in smem so AV loop can roll over j
        #pragma unroll
        for (int j = 0; j < KT; j += 4) {
            float4 pv;
            pv.x = __expf(s[j]   - m);
            pv.y = __expf(s[j+1] - m);
            pv.z = __expf(s[j+2] - m);
            pv.w = __expf(s[j+3] - m);
            l += pv.x + pv.y + pv.z + pv.w;
            *reinterpret_cast<float4*>(&ps[tid*LDQ + j]) = pv;
        }
        // o += p_j * v_j
        #pragma unroll 1
        for (int j = 0; j < KT; j++) {
            float p = ps[tid*LDQ + j];
            #pragma unroll
            for (int d = 0; d < NDH; d += 4) {
                float4 vj = *reinterpret_cast<const float4*>(&vs[j*LDQ + d]);
                o[d]   += p*vj.x;
                o[d+1] += p*vj.y;
                o[d+2] += p*vj.z;
                o[d+3] += p*vj.w;
            }
        }
    }
    float inv = 1.f / l;
    #pragma unroll
    for (int d = 0; d < NDH; d += 4) {
        float4 w;
        w.x = o[d]*inv; w.y = o[d+1]*inv; w.z = o[d+2]*inv; w.w = o[d+3]*inv;
        *reinterpret_cast<float4*>(&out[((size_t)(b*NS + i))*ND + h*NDH + d]) = w;
    }
}

// ---------------- residual add + LayerNorm (in place on x) ----------------
__global__ __launch_bounds__(256) void add_ln_kernel(
    float* __restrict__ x, const float* __restrict__ y,
    const float* __restrict__ gw, const float* __restrict__ bw)
{
    __shared__ float buf[ND];
    __shared__ float red[33];
    int row = blockIdx.x;
    int tid = threadIdx.x;
    size_t base = (size_t)row * ND;

    float s = 0.f;
    for (int d = tid; d < ND; d += 256) {
        float t = x[base + d] + y[base + d];
        buf[d] = t;
        s += t;
    }
    #pragma unroll
    for (int off = 16; off; off >>= 1) s += __shfl_xor_sync(0xffffffffu, s, off);
    if ((tid & 31) == 0) red[tid >> 5] = s;
    __syncthreads();
    if (tid < 32) {
        float v2 = (tid < 8) ? red[tid] : 0.f;
        #pragma unroll
        for (int off = 4; off; off >>= 1) v2 += __shfl_xor_sync(0xffffffffu, v2, off);
        if (tid == 0) red[32] = v2;
    }
    __syncthreads();
    float mean = red[32] * (1.f/ND);

    float sv = 0.f;
    for (int d = tid; d < ND; d += 256) {
        float t = buf[d] - mean;
        sv += t*t;
    }
    #pragma unroll
    for (int off = 16; off; off >>= 1) sv += __shfl_xor_sync(0xffffffffu, sv, off);
    __syncthreads();
    if ((tid & 31) == 0) red[tid >> 5] = sv;
    __syncthreads();
    if (tid < 32) {
        float v2 = (tid < 8) ? red[tid] : 0.f;
        #pragma unroll
        for (int off = 4; off; off >>= 1) v2 += __shfl_xor_sync(0xffffffffu, v2, off);
        if (tid == 0) red[32] = v2;
    }
    __syncthreads();
    float inv = rsqrtf(red[32] * (1.f/ND) + 1e-5f);
    for (int d = tid; d < ND; d += 256)
        x[base + d] = (buf[d] - mean) * inv * gw[d] + bw[d];
}

// ---------------- host orchestration ----------------
extern "C" void kernel_launch(void* const* d_in, const int* in_sizes, int n_in,
                              void* d_out, int out_size)
{
    (void)in_sizes; (void)n_in; (void)out_size;
    const int*   tgt = (const int*)d_in[0];
    const float* emb = (const float*)d_in[1];
    const float* Wq  = (const float*)d_in[2];
    const float* bq  = (const float*)d_in[3];
    const float* Wk  = (const float*)d_in[4];
    const float* bk  = (const float*)d_in[5];
    const float* Wv  = (const float*)d_in[6];
    const float* bv  = (const float*)d_in[7];
    const float* Wo  = (const float*)d_in[8];
    const float* bo  = (const float*)d_in[9];
    const float* rel = (const float*)d_in[10];
    const float* W1  = (const float*)d_in[11];
    const float* b1  = (const float*)d_in[12];
    const float* W2  = (const float*)d_in[13];
    const float* b2  = (const float*)d_in[14];
    const float* g1  = (const float*)d_in[15];
    const float* be1 = (const float*)d_in[16];
    const float* g2  = (const float*)d_in[17];
    const float* be2 = (const float*)d_in[18];
    const float* Wf  = (const float*)d_in[19];
    const float* bf  = (const float*)d_in[20];
    float* logits = (float*)d_out;

    float *x_, *q_, *k_, *v_, *o_, *t_, *h_, *qr_;
    cudaGetSymbolAddress((void**)&x_,  g_x);
    cudaGetSymbolAddress((void**)&q_,  g_q);
    cudaGetSymbolAddress((void**)&k_,  g_k);
    cudaGetSymbolAddress((void**)&v_,  g_v);
    cudaGetSymbolAddress((void**)&o_,  g_o);
    cudaGetSymbolAddress((void**)&t_,  g_t);
    cudaGetSymbolAddress((void**)&h_,  g_h);
    cudaGetSymbolAddress((void**)&qr_, g_qr);

    int attn_smem = (QT*LDQ + KT*LDQ + KT*LDQ + QT*LDQ)*(int)sizeof(float) + KT*(int)sizeof(int);
    cudaFuncSetAttribute(attn_kernel, cudaFuncAttributeMaxDynamicSharedMemorySize, attn_smem);

    embed_kernel<<<NROWS*ND/4/256, 256>>>(tgt, emb, x_);

    dim3 thr(256);
    for (int l = 0; l < NL; l++) {
        const float* Wql = Wq + (size_t)l*ND*ND;
        const float* Wkl = Wk + (size_t)l*ND*ND;
        const float* Wvl = Wv + (size_t)l*ND*ND;
        const float* Wol = Wo + (size_t)l*ND*ND;

        dim3 gDD(ND/BN, NROWS/BM);                       // (8,16)
        gemm_nt<<<gDD, thr>>>(q_, x_, Wql, bq + l*ND, NROWS, ND, ND, 0.125f, 0);
        gemm_nt<<<gDD, thr>>>(k_, x_, Wkl, bk + l*ND, NROWS, ND, ND, 1.f, 0);
        gemm_nt<<<gDD, thr>>>(v_, x_, Wvl, bv + l*ND, NROWS, ND, ND, 1.f, 0);

        // QR[bsh, r] = q_row . rel[l][r]   (M=32768, N=2047, K=64)
        dim3 gQR((NR + BN - 1)/BN, NROWS*NH/BM);         // (16,256)
        gemm_nt<<<gQR, thr>>>(qr_, q_, rel + (size_t)l*NR*NDH, (const float*)nullptr,
                              NROWS*NH, NR, NDH, 1.f, 0);

        attn_kernel<<<dim3(NS/QT, NH, NB), 128, attn_smem>>>(o_, q_, k_, v_, qr_, tgt);

        gemm_nt<<<gDD, thr>>>(t_, o_, Wol, bo + l*ND, NROWS, ND, ND, 1.f, 0);
        add_ln_kernel<<<NROWS, 256>>>(x_, t_, g1 + l*ND, be1 + l*ND);

        dim3 gF1(NDFF/BN, NROWS/BM);                     // (32,16)
        gemm_nt<<<gF1, thr>>>(h_, x_, W1 + (size_t)l*NDFF*ND, b1 + l*NDFF,
                              NROWS, NDFF, ND, 1.f, 1);
        gemm_nt<<<gDD, thr>>>(t_, h_, W2 + (size_t)l*ND*NDFF, b2 + l*ND,
                              NROWS, ND, NDFF, 1.f, 0);
        add_ln_kernel<<<NROWS, 256>>>(x_, t_, g2 + l*ND, be2 + l*ND);
    }

    dim3 gFin(NV/BN, NROWS/BM);                          // (250,16)
    gemm_nt<<<gFin, thr>>>(logits, x_, Wf, bf, NROWS, NV, ND, 1.f, 0);
}

// round 3
// speedup vs baseline: 1.9919x; 1.9919x over previous
#include <cuda_runtime.h>
#include <cuda_bf16.h>
#include <cstdint>
#include <math.h>

// ---------------- problem constants ----------------
#define NB 2
#define NS 1024
#define ND 1024
#define NH 16
#define NDH 64
#define NL 4
#define NDFF 4096
#define NV 32000
#define NR 2047              // 2*MAXLEN-1
#define NROWS (NB*NS)        // 2048

// ---------------- scratch (static device allocations) ----------------
__device__ float g_x[NROWS*ND];
__device__ float g_q[NROWS*ND];
__device__ float g_k[NROWS*ND];
__device__ float g_v[NROWS*ND];
__device__ float g_o[NROWS*ND];
__device__ float g_t[NROWS*ND];
__device__ float g_h[NROWS*NDFF];
__device__ float g_qr[(size_t)NROWS*NH*NR];   // [B*S*H, 2047]

// split-bf16 operand buffers
__device__ __nv_bfloat16 g_Ah[(size_t)NROWS*NDFF];
__device__ __nv_bfloat16 g_Al[(size_t)NROWS*NDFF];
__device__ __nv_bfloat16 g_Bh[(size_t)NV*ND];
__device__ __nv_bfloat16 g_Bl[(size_t)NV*ND];

// ---------------- helpers ----------------
__device__ __forceinline__ uint32_t smem_u32(const void* p) {
    uint32_t a;
    asm("{ .reg .u64 t; cvta.to.shared.u64 t, %1; cvt.u32.u64 %0, t; }" : "=r"(a) : "l"(p));
    return a;
}

#define LDSM4(r, a) \
    asm volatile("ldmatrix.sync.aligned.m8n8.x4.shared.b16 {%0,%1,%2,%3}, [%4];" \
        : "=r"((r)[0]), "=r"((r)[1]), "=r"((r)[2]), "=r"((r)[3]) : "r"(a))
#define LDSM2(r, a) \
    asm volatile("ldmatrix.sync.aligned.m8n8.x2.shared.b16 {%0,%1}, [%2];" \
        : "=r"((r)[0]), "=r"((r)[1]) : "r"(a))

#define MMA16816(d, a, b) \
    asm volatile("mma.sync.aligned.m16n8k16.row.col.f32.bf16.bf16.f32 " \
        "{%0,%1,%2,%3}, {%4,%5,%6,%7}, {%8,%9}, {%0,%1,%2,%3};" \
        : "+f"((d)[0]), "+f"((d)[1]), "+f"((d)[2]), "+f"((d)[3]) \
        : "r"((a)[0]), "r"((a)[1]), "r"((a)[2]), "r"((a)[3]), "r"((b)[0]), "r"((b)[1]))

#define CP_ASYNC16(dst, src, sz) \
    asm volatile("cp.async.cg.shared.global [%0], [%1], 16, %2;" \
        :: "r"(dst), "l"(src), "r"(sz))
#define CP_COMMIT() asm volatile("cp.async.commit_group;")
#define CP_WAIT0()  asm volatile("cp.async.wait_group 0;")
#define CP_WAIT1()  asm volatile("cp.async.wait_group 1;")

// ---------------- fp32 -> bf16 hi/lo split ----------------
__global__ void split_kernel(const float4* __restrict__ src,
                             __nv_bfloat16* __restrict__ hi,
                             __nv_bfloat16* __restrict__ lo, int n4) {
    int i = blockIdx.x * 256 + threadIdx.x;
    if (i >= n4) return;
    float4 v = src[i];
    __nv_bfloat16 h0 = __float2bfloat16(v.x);
    __nv_bfloat16 h1 = __float2bfloat16(v.y);
    __nv_bfloat16 h2 = __float2bfloat16(v.z);
    __nv_bfloat16 h3 = __float2bfloat16(v.w);
    __nv_bfloat16 l0 = __float2bfloat16(v.x - __bfloat162float(h0));
    __nv_bfloat16 l1 = __float2bfloat16(v.y - __bfloat162float(h1));
    __nv_bfloat16 l2 = __float2bfloat16(v.z - __bfloat162float(h2));
    __nv_bfloat16 l3 = __float2bfloat16(v.w - __bfloat162float(h3));
    __nv_bfloat162* H = reinterpret_cast<__nv_bfloat162*>(hi);
    __nv_bfloat162* L = reinterpret_cast<__nv_bfloat162*>(lo);
    H[i*2+0] = __nv_bfloat162(h0, h1);
    H[i*2+1] = __nv_bfloat162(h2, h3);
    L[i*2+0] = __nv_bfloat162(l0, l1);
    L[i*2+1] = __nv_bfloat162(l2, l3);
}

// ---------------- embedding: x = emb[tgt] * sqrt(D) ----------------
__global__ void embed_kernel(const int* __restrict__ tgt,
                             const float* __restrict__ emb,
                             float* __restrict__ x) {
    int idx = blockIdx.x * blockDim.x + threadIdx.x;
    int row = idx >> 8;
    int c4  = idx & 255;
    float4 v = reinterpret_cast<const float4*>(emb + (size_t)tgt[row] * ND)[c4];
    v.x *= 32.f; v.y *= 32.f; v.z *= 32.f; v.w *= 32.f;
    reinterpret_cast<float4*>(x)[idx] = v;
}

// ---------------- split-bf16 tensor-core GEMM (mma.sync) ----------------
// C[M,N] = alpha*((Ahi+Alo)[M,K] @ (Bhi+Blo)[N,K]^T + bias), optional relu.
// CTA tile 128x128, k-tile 32, 8 warps (2x4), warp tile 64x32.
// smem per stage: Ah(8K) Al(8K) Bh(8K) Bl(8K) = 32KB, 2 stages = 64KB.
#define STG 32768
#define TOFF 8192
#define GEMM_SMEM (2*STG)

// one 128x32 bf16 tile, swizzled: phys = row*64B + ((chunk ^ ((row>>1)&3))*16B)
__device__ __forceinline__ void ld_tile_async(
    uint32_t sbase, const __nv_bfloat16* __restrict__ g,
    int ldk, int row0, int k0, int rmax, int tid)
{
    #pragma unroll
    for (int it = 0; it < 2; it++) {
        int qq = tid + it * 256;
        int r = qq >> 2, c = qq & 3;
        uint32_t dst = sbase + r * 64 + ((c ^ ((r >> 1) & 3)) << 4);
        int rr = (r < rmax) ? r : 0;
        const __nv_bfloat16* src = g + (size_t)(row0 + rr) * ldk + k0 + c * 8;
        int sz = (r < rmax) ? 16 : 0;
        CP_ASYNC16(dst, src, sz);
    }
}

__global__ __launch_bounds__(256) void gemm_tc(
    float* __restrict__ C,
    const __nv_bfloat16* __restrict__ Ah, const __nv_bfloat16* __restrict__ Al,
    const __nv_bfloat16* __restrict__ Bh, const __nv_bfloat16* __restrict__ Bl,
    const float* __restrict__ bias, int M, int N, int K, float alpha, int relu)
{
    extern __shared__ char sm[];
    uint32_t smb = smem_u32(sm);
    int tid = threadIdx.x;
    int wid = tid >> 5;
    int lane = tid & 31;
    int wm = wid & 1;          // 2 warps along M
    int wn = wid >> 1;         // 4 warps along N
    int m0 = blockIdx.y * 128;
    int n0 = blockIdx.x * 128;
    int NT = K >> 5;
    int bn = N - n0; if (bn > 128) bn = 128;

    // prologue: stages 0,1
    {
        uint32_t s0 = smb;
        ld_tile_async(s0 + 0*TOFF, Ah, K, m0, 0, 128, tid);
        ld_tile_async(s0 + 1*TOFF, Al, K, m0, 0, 128, tid);
        ld_tile_async(s0 + 2*TOFF, Bh, K, n0, 0, bn, tid);
        ld_tile_async(s0 + 3*TOFF, Bl, K, n0, 0, bn, tid);
        CP_COMMIT();
        if (NT > 1) {
            uint32_t s1 = smb + STG;
            ld_tile_async(s1 + 0*TOFF, Ah, K, m0, 32, 128, tid);
            ld_tile_async(s1 + 1*TOFF, Al, K, m0, 32, 128, tid);
            ld_tile_async(s1 + 2*TOFF, Bh, K, n0, 32, bn, tid);
            ld_tile_async(s1 + 3*TOFF, Bl, K, n0, 32, bn, tid);
            CP_COMMIT();
        }
    }

    float acc[4][4][4];
    #pragma unroll
    for (int i = 0; i < 4; i++)
        #pragma unroll
        for (int j = 0; j < 4; j++)
            #pragma unroll
            for (int e = 0; e < 4; e++) acc[i][j][e] = 0.f;

    for (int kt = 0; kt < NT; kt++) {
        if (kt + 1 < NT) { CP_WAIT1(); } else { CP_WAIT0(); }
        __syncthreads();

        uint32_t sA = smb + (kt & 1) * STG;
        uint32_t sB = sA + 2*TOFF;

        #pragma unroll
        for (int ks = 0; ks < 2; ks++) {
            uint32_t ah[4][4], al[4][4], bh[4][2], bl[4][2];
            #pragma unroll
            for (int mf = 0; mf < 4; mf++) {
                int row = wm * 64 + mf * 16 + (lane & 15);
                int cc = ks * 2 + (lane >> 4);
                uint32_t ad = sA + row * 64 + (((cc ^ ((row >> 1) & 3))) << 4);
                LDSM4(ah[mf], ad);
                LDSM4(al[mf], ad + TOFF);
            }
            #pragma unroll
            for (int nf = 0; nf < 4; nf++) {
                int rn = wn * 32 + nf * 8 + (lane & 7);
                int cc = ks * 2 + ((lane >> 3) & 1);
                uint32_t bd = sB + rn * 64 + (((cc ^ ((rn >> 1) & 3))) << 4);
                LDSM2(bh[nf], bd);
                LDSM2(bl[nf], bd + TOFF);
            }
            #pragma unroll
            for (int mf = 0; mf < 4; mf++)
                #pragma unroll
                for (int nf = 0; nf < 4; nf++) {
                    MMA16816(acc[mf][nf], ah[mf], bh[nf]);
                    MMA16816(acc[mf][nf], ah[mf], bl[nf]);
                    MMA16816(acc[mf][nf], al[mf], bh[nf]);
                }
        }
        __syncthreads();

        if (kt + 2 < NT) {
            uint32_t sN = smb + (kt & 1) * STG;
            int k0 = (kt + 2) << 5;
            ld_tile_async(sN + 0*TOFF, Ah, K, m0, k0, 128, tid);
            ld_tile_async(sN + 1*TOFF, Al, K, m0, k0, 128, tid);
            ld_tile_async(sN + 2*TOFF, Bh, K, n0, k0, bn, tid);
            ld_tile_async(sN + 3*TOFF, Bl, K, n0, k0, bn, tid);
            CP_COMMIT();
        }
    }

    // epilogue
    bool fast = ((N & 1) == 0) && (n0 + 128 <= N);
    #pragma unroll
    for (int mf = 0; mf < 4; mf++) {
        int r0 = m0 + wm * 64 + mf * 16 + (lane >> 2);
        #pragma unroll
        for (int half = 0; half < 2; half++) {
            int row = r0 + half * 8;
            float* crow = C + (size_t)row * N;
            #pragma unroll
            for (int nf = 0; nf < 4; nf++) {
                int col = n0 + wn * 32 + nf * 8 + (lane & 3) * 2;
                float v0 = acc[mf][nf][half * 2 + 0];
                float v1 = acc[mf][nf][half * 2 + 1];
                if (bias) { v0 += bias[col]; v1 += __ldg(&bias[col + 1]); }
                v0 *= alpha; v1 *= alpha;
                if (relu) { v0 = fmaxf(v0, 0.f); v1 = fmaxf(v1, 0.f); }
                if (fast) {
                    *reinterpret_cast<float2*>(crow + col) = make_float2(v0, v1);
                } else {
                    if (col < N)     crow[col] = v0;
                    if (col + 1 < N) crow[col + 1] = v1;
                }
            }
        }
    }
}

// ---------------- fused attention (flash-style, exact softmax semantics) ----------------
#define QT 128
#define KT 64
#define LDQ 68

__global__ __launch_bounds__(128) void attn_kernel(
    float* __restrict__ out, const float* __restrict__ q, const float* __restrict__ k,
    const float* __restrict__ v, const float* __restrict__ qr, const int* __restrict__ tgt)
{
    extern __shared__ float smf[];
    float* qs = smf;
    float* ks = qs + QT*LDQ;
    float* vs = ks + KT*LDQ;
    float* ps = vs + KT*LDQ;
    int*   pf = (int*)(ps + QT*LDQ);

    int b = blockIdx.z, h = blockIdx.y;
    int tid = threadIdx.x;
    int i0 = blockIdx.x * QT;
    int i  = i0 + tid;

    for (int t = tid; t < QT*NDH/4; t += 128) {
        int r  = t >> 4;
        int c4 = (t & 15) << 2;
        float4 va = *reinterpret_cast<const float4*>(
            &q[((size_t)(b*NS + i0 + r))*ND + h*NDH + c4]);
        *reinterpret_cast<float4*>(&qs[r*LDQ + c4]) = va;
    }

    float o[NDH];
    #pragma unroll
    for (int d = 0; d < NDH; d++) o[d] = 0.f;
    float m = -1e30f, l = 0.f;
    const float* qrrow = qr + ((size_t)((b*NS + i)*NH + h)) * NR + (1023 - i);

    for (int j0 = 0; j0 < NS; j0 += KT) {
        __syncthreads();
        for (int t = tid; t < KT*NDH/4; t += 128) {
            int r  = t >> 4;
            int c4 = (t & 15) << 2;
            size_t g = ((size_t)(b*NS + j0 + r))*ND + h*NDH + c4;
            *reinterpret_cast<float4*>(&ks[r*LDQ + c4]) =
                *reinterpret_cast<const float4*>(&k[g]);
            *reinterpret_cast<float4*>(&vs[r*LDQ + c4]) =
                *reinterpret_cast<const float4*>(&v[g]);
        }
        if (tid < KT) pf[tid] = (tgt[b*NS + j0 + tid] == 0) ? 1 : 0;
        __syncthreads();

        float s[KT];
        #pragma unroll
        for (int j = 0; j < KT; j++) s[j] = 0.f;
        #pragma unroll 1
        for (int d = 0; d < NDH; d += 4) {
            float4 qd = *reinterpret_cast<const float4*>(&qs[tid*LDQ + d]);
            #pragma unroll
            for (int j = 0; j < KT; j++) {
                float4 kj = *reinterpret_cast<const float4*>(&ks[j*LDQ + d]);
                s[j] += qd.x*kj.x + qd.y*kj.y + qd.z*kj.z + qd.w*kj.w;
            }
        }
        float mt = m;
        #pragma unroll
        for (int j = 0; j < KT; j++) {
            int jj = j0 + j;
            float val = s[j] + qrrow[jj];
            if (jj > i || pf[j]) val = -1e9f;
            s[j] = val;
            mt = fmaxf(mt, val);
        }
        float corr = __expf(m - mt);
        m = mt;
        l *= corr;
        #pragma unroll
        for (int d = 0; d < NDH; d++) o[d] *= corr;
        #pragma unroll
        for (int j = 0; j < KT; j += 4) {
            float4 pv;
            pv.x = __expf(s[j]   - m);
            pv.y = __expf(s[j+1] - m);
            pv.z = __expf(s[j+2] - m);
            pv.w = __expf(s[j+3] - m);
            l += pv.x + pv.y + pv.z + pv.w;
            *reinterpret_cast<float4*>(&ps[tid*LDQ + j]) = pv;
        }
        #pragma unroll 1
        for (int j = 0; j < KT; j++) {
            float p = ps[tid*LDQ + j];
            #pragma unroll
            for (int d = 0; d < NDH; d += 4) {
                float4 vj = *reinterpret_cast<const float4*>(&vs[j*LDQ + d]);
                o[d]   += p*vj.x;
                o[d+1] += p*vj.y;
                o[d+2] += p*vj.z;
                o[d+3] += p*vj.w;
            }
        }
    }
    float inv = 1.f / l;
    #pragma unroll
    for (int d = 0; d < NDH; d += 4) {
        float4 w;
        w.x = o[d]*inv; w.y = o[d+1]*inv; w.z = o[d+2]*inv; w.w = o[d+3]*inv;
        *reinterpret_cast<float4*>(&out[((size_t)(b*NS + i))*ND + h*NDH + d]) = w;
    }
}

// ---------------- residual add + LayerNorm (in place on x) ----------------
__global__ __launch_bounds__(256) void add_ln_kernel(
    float* __restrict__ x, const float* __restrict__ y,
    const float* __restrict__ gw, const float* __restrict__ bw)
{
    __shared__ float buf[ND];
    __shared__ float red[33];
    int row = blockIdx.x;
    int tid = threadIdx.x;
    size_t base = (size_t)row * ND;

    float s = 0.f;
    for (int d = tid; d < ND; d += 256) {
        float t = x[base + d] + y[base + d];
        buf[d] = t;
        s += t;
    }
    #pragma unroll
    for (int off = 16; off; off >>= 1) s += __shfl_xor_sync(0xffffffffu, s, off);
    if ((tid & 31) == 0) red[tid >> 5] = s;
    __syncthreads();
    if (tid < 32) {
        float v2 = (tid < 8) ? red[tid] : 0.f;
        #pragma unroll
        for (int off = 4; off; off >>= 1) v2 += __shfl_xor_sync(0xffffffffu, v2, off);
        if (tid == 0) red[32] = v2;
    }
    __syncthreads();
    float mean = red[32] * (1.f/ND);

    float sv = 0.f;
    for (int d = tid; d < ND; d += 256) {
        float t = buf[d] - mean;
        sv += t*t;
    }
    #pragma unroll
    for (int off = 16; off; off >>= 1) sv += __shfl_xor_sync(0xffffffffu, sv, off);
    __syncthreads();
    if ((tid & 31) == 0) red[tid >> 5] = sv;
    __syncthreads();
    if (tid < 32) {
        float v2 = (tid < 8) ? red[tid] : 0.f;
        #pragma unroll
        for (int off = 4; off; off >>= 1) v2 += __shfl_xor_sync(0xffffffffu, v2, off);
        if (tid == 0) red[32] = v2;
    }
    __syncthreads();
    float inv = rsqrtf(red[32] * (1.f/ND) + 1e-5f);
    for (int d = tid; d < ND; d += 256)
        x[base + d] = (buf[d] - mean) * inv * gw[d] + bw[d];
}

// ---------------- host orchestration ----------------
static inline void split(const float* src, __nv_bfloat16* hi, __nv_bfloat16* lo, size_t n) {
    int n4 = (int)(n / 4);
    split_kernel<<<(n4 + 255) / 256, 256>>>(
        reinterpret_cast<const float4*>(src), hi, lo, n4);
}

extern "C" void kernel_launch(void* const* d_in, const int* in_sizes, int n_in,
                              void* d_out, int out_size)
{
    (void)in_sizes; (void)n_in; (void)out_size;
    const int*   tgt = (const int*)d_in[0];
    const float* emb = (const float*)d_in[1];
    const float* Wq  = (const float*)d_in[2];
    const float* bq  = (const float*)d_in[3];
    const float* Wk  = (const float*)d_in[4];
    const float* bk  = (const float*)d_in[5];
    const float* Wv  = (const float*)d_in[6];
    const float* bv  = (const float*)d_in[7];
    const float* Wo  = (const float*)d_in[8];
    const float* bo  = (const float*)d_in[9];
    const float* rel = (const float*)d_in[10];
    const float* W1  = (const float*)d_in[11];
    const float* b1  = (const float*)d_in[12];
    const float* W2  = (const float*)d_in[13];
    const float* b2  = (const float*)d_in[14];
    const float* g1  = (const float*)d_in[15];
    const float* be1 = (const float*)d_in[16];
    const float* g2  = (const float*)d_in[17];
    const float* be2 = (const float*)d_in[18];
    const float* Wf  = (const float*)d_in[19];
    const float* bf  = (const float*)d_in[20];
    float* logits = (float*)d_out;

    float *x_, *q_, *k_, *v_, *o_, *t_, *h_, *qr_;
    __nv_bfloat16 *Ah, *Al, *Bh, *Bl;
    cudaGetSymbolAddress((void**)&x_,  g_x);
    cudaGetSymbolAddress((void**)&q_,  g_q);
    cudaGetSymbolAddress((void**)&k_,  g_k);
    cudaGetSymbolAddress((void**)&v_,  g_v);
    cudaGetSymbolAddress((void**)&o_,  g_o);
    cudaGetSymbolAddress((void**)&t_,  g_t);
    cudaGetSymbolAddress((void**)&h_,  g_h);
    cudaGetSymbolAddress((void**)&qr_, g_qr);
    cudaGetSymbolAddress((void**)&Ah,  g_Ah);
    cudaGetSymbolAddress((void**)&Al,  g_Al);
    cudaGetSymbolAddress((void**)&Bh,  g_Bh);
    cudaGetSymbolAddress((void**)&Bl,  g_Bl);

    int attn_smem = (QT*LDQ + KT*LDQ + KT*LDQ + QT*LDQ)*(int)sizeof(float) + KT*(int)sizeof(int);
    cudaFuncSetAttribute(attn_kernel, cudaFuncAttributeMaxDynamicSharedMemorySize, attn_smem);
    cudaFuncSetAttribute(gemm_tc, cudaFuncAttributeMaxDynamicSharedMemorySize, GEMM_SMEM);

    embed_kernel<<<NROWS*ND/4/256, 256>>>(tgt, emb, x_);

    for (int l = 0; l < NL; l++) {
        const size_t WDD = (size_t)ND*ND;
        // q/k/v projections
        split(x_, Ah, Al, (size_t)NROWS*ND);
        split(Wq + l*WDD, Bh, Bl, WDD);
        gemm_tc<<<dim3(ND/128, NROWS/128), 256, GEMM_SMEM>>>(
            q_, Ah, Al, Bh, Bl, bq + l*ND, NROWS, ND, ND, 0.125f, 0);
        split(Wk + l*WDD, Bh, Bl, WDD);
        gemm_tc<<<dim3(ND/128, NROWS/128), 256, GEMM_SMEM>>>(
            k_, Ah, Al, Bh, Bl, bk + l*ND, NROWS, ND, ND, 1.f, 0);
        split(Wv + l*WDD, Bh, Bl, WDD);
        gemm_tc<<<dim3(ND/128, NROWS/128), 256, GEMM_SMEM>>>(
            v_, Ah, Al, Bh, Bl, bv + l*ND, NROWS, ND, ND, 1.f, 0);

        // QR[bsh, r] = q . rel^T : M=32768, N=2047, K=64
        split(q_, Ah, Al, (size_t)NROWS*ND);
        split(rel + (size_t)l*NR*NDH, Bh, Bl, (size_t)NR*NDH);
        gemm_tc<<<dim3((NR + 127)/128, NROWS*NH/128), 256, GEMM_SMEM>>>(
            qr_, Ah, Al, Bh, Bl, (const float*)nullptr, NROWS*NH, NR, NDH, 1.f, 0);

        attn_kernel<<<dim3(NS/QT, NH, NB), 128, attn_smem>>>(o_, q_, k_, v_, qr_, tgt);

        // output projection + LN
        split(o_, Ah, Al, (size_t)NROWS*ND);
        split(Wo + l*WDD, Bh, Bl, WDD);
        gemm_tc<<<dim3(ND/128, NROWS/128), 256, GEMM_SMEM>>>(
            t_, Ah, Al, Bh, Bl, bo + l*ND, NROWS, ND, ND, 1.f, 0);
        add_ln_kernel<<<NROWS, 256>>>(x_, t_, g1 + l*ND, be1 + l*ND);

        // FFN
        split(x_, Ah, Al, (size_t)NROWS*ND);
        split(W1 + (size_t)l*NDFF*ND, Bh, Bl, (size_t)NDFF*ND);
        gemm_tc<<<dim3(NDFF/128, NROWS/128), 256, GEMM_SMEM>>>(
            h_, Ah, Al, Bh, Bl, b1 + l*NDFF, NROWS, NDFF, ND, 1.f, 1);
        split(h_, Ah, Al, (size_t)NROWS*NDFF);
        split(W2 + (size_t)l*ND*NDFF, Bh, Bl, (size_t)ND*NDFF);
        gemm_tc<<<dim3(ND/128, NROWS/128), 256, GEMM_SMEM>>>(
            t_, Ah, Al, Bh, Bl, b2 + l*ND, NROWS, ND, NDFF, 1.f, 0);
        add_ln_kernel<<<NROWS, 256>>>(x_, t_, g2 + l*ND, be2 + l*ND);
    }

    // final logits: M=2048, N=32000, K=1024
    split(x_, Ah, Al, (size_t)NROWS*ND);
    split(Wf, Bh, Bl, (size_t)NV*ND);
    gemm_tc<<<dim3(NV/128, NROWS/128), 256, GEMM_SMEM>>>(
        logits, Ah, Al, Bh, Bl, bf, NROWS, NV, ND, 1.f, 0);
}

// round 4
// speedup vs baseline: 2.0663x; 1.0373x over previous
#include <cuda_runtime.h>
#include <cuda_bf16.h>
#include <cstdint>
#include <math.h>

// ---------------- problem constants ----------------
#define NB 2
#define NS 1024
#define ND 1024
#define NH 16
#define NDH 64
#define NL 4
#define NDFF 4096
#define NV 32000
#define NR 2047              // 2*MAXLEN-1
#define NROWS (NB*NS)        // 2048

// ---------------- scratch (static device allocations) ----------------
__device__ float g_x[NROWS*ND];
__device__ float g_q[NROWS*ND];
__device__ float g_k[NROWS*ND];
__device__ float g_v[NROWS*ND];
__device__ float g_o[NROWS*ND];
__device__ float g_t[NROWS*ND];
__device__ float g_h[NROWS*NDFF];
__device__ float g_qr[(size_t)NROWS*NH*NR];   // [B*S*H, 2047]

// split-bf16 operand buffers
__device__ __nv_bfloat16 g_Ah[(size_t)NROWS*NDFF];
__device__ __nv_bfloat16 g_Al[(size_t)NROWS*NDFF];
__device__ __nv_bfloat16 g_Bh[(size_t)NV*ND];
__device__ __nv_bfloat16 g_Bl[(size_t)NV*ND];

// ---------------- helpers ----------------
__device__ __forceinline__ uint32_t smem_u32(const void* p) {
    uint32_t a;
    asm("{ .reg .u64 t; cvta.to.shared.u64 t, %1; cvt.u32.u64 %0, t; }" : "=r"(a) : "l"(p));
    return a;
}

#define LDSM4(r, a) \
    asm volatile("ldmatrix.sync.aligned.m8n8.x4.shared.b16 {%0,%1,%2,%3}, [%4];" \
        : "=r"((r)[0]), "=r"((r)[1]), "=r"((r)[2]), "=r"((r)[3]) : "r"(a))
#define LDSM2(r, a) \
    asm volatile("ldmatrix.sync.aligned.m8n8.x2.shared.b16 {%0,%1}, [%2];" \
        : "=r"((r)[0]), "=r"((r)[1]) : "r"(a))

#define MMA16816(d, a, b) \
    asm volatile("mma.sync.aligned.m16n8k16.row.col.f32.bf16.bf16.f32 " \
        "{%0,%1,%2,%3}, {%4,%5,%6,%7}, {%8,%9}, {%0,%1,%2,%3};" \
        : "+f"((d)[0]), "+f"((d)[1]), "+f"((d)[2]), "+f"((d)[3]) \
        : "r"((a)[0]), "r"((a)[1]), "r"((a)[2]), "r"((a)[3]), "r"((b)[0]), "r"((b)[1]))

#define CP_ASYNC16(dst, src, sz) \
    asm volatile("cp.async.cg.shared.global [%0], [%1], 16, %2;" \
        :: "r"(dst), "l"(src), "r"(sz))
#define CP_COMMIT() asm volatile("cp.async.commit_group;")
#define CP_WAIT0()  asm volatile("cp.async.wait_group 0;")
#define CP_WAIT1()  asm volatile("cp.async.wait_group 1;")

// ---------------- fp32 -> bf16 hi/lo split ----------------
__global__ void split_kernel(const float4* __restrict__ src,
                             __nv_bfloat16* __restrict__ hi,
                             __nv_bfloat16* __restrict__ lo, int n4) {
    int i = blockIdx.x * 256 + threadIdx.x;
    if (i >= n4) return;
    float4 v = src[i];
    __nv_bfloat16 h0 = __float2bfloat16(v.x);
    __nv_bfloat16 h1 = __float2bfloat16(v.y);
    __nv_bfloat16 h2 = __float2bfloat16(v.z);
    __nv_bfloat16 h3 = __float2bfloat16(v.w);
    __nv_bfloat16 l0 = __float2bfloat16(v.x - __bfloat162float(h0));
    __nv_bfloat16 l1 = __float2bfloat16(v.y - __bfloat162float(h1));
    __nv_bfloat16 l2 = __float2bfloat16(v.z - __bfloat162float(h2));
    __nv_bfloat16 l3 = __float2bfloat16(v.w - __bfloat162float(h3));
    __nv_bfloat162* H = reinterpret_cast<__nv_bfloat162*>(hi);
    __nv_bfloat162* L = reinterpret_cast<__nv_bfloat162*>(lo);
    H[i*2+0] = __nv_bfloat162(h0, h1);
    H[i*2+1] = __nv_bfloat162(h2, h3);
    L[i*2+0] = __nv_bfloat162(l0, l1);
    L[i*2+1] = __nv_bfloat162(l2, l3);
}

// ---------------- embedding: x = emb[tgt] * sqrt(D) ----------------
__global__ void embed_kernel(const int* __restrict__ tgt,
                             const float* __restrict__ emb,
                             float* __restrict__ x) {
    int idx = blockIdx.x * blockDim.x + threadIdx.x;
    int row = idx >> 8;
    int c4  = idx & 255;
    float4 v = reinterpret_cast<const float4*>(emb + (size_t)tgt[row] * ND)[c4];
    v.x *= 32.f; v.y *= 32.f; v.z *= 32.f; v.w *= 32.f;
    reinterpret_cast<float4*>(x)[idx] = v;
}

// ---------------- split-bf16 tensor-core GEMM (mma.sync) ----------------
// C[M,N] = alpha*((Ahi+Alo)[M,K] @ (Bhi+Blo)[N,K]^T + bias), optional relu.
// CTA tile 128x128, k-tile 32, 8 warps (2x4), warp tile 64x32, 3-stage pipeline.
#define STG 32768
#define TOFF 8192
#define GEMM_SMEM (3*STG)

// one 128x32 bf16 tile, swizzled: phys = row*64B + ((chunk ^ ((row>>1)&3))*16B)
__device__ __forceinline__ void ld_tile_async(
    uint32_t sbase, const __nv_bfloat16* __restrict__ g,
    int ldk, int row0, int k0, int rmax, int tid)
{
    #pragma unroll
    for (int it = 0; it < 2; it++) {
        int qq = tid + it * 256;
        int r = qq >> 2, c = qq & 3;
        uint32_t dst = sbase + r * 64 + ((c ^ ((r >> 1) & 3)) << 4);
        int rr = (r < rmax) ? r : 0;
        const __nv_bfloat16* src = g + (size_t)(row0 + rr) * ldk + k0 + c * 8;
        int sz = (r < rmax) ? 16 : 0;
        CP_ASYNC16(dst, src, sz);
    }
}

__device__ __forceinline__ void ld_stage(
    uint32_t sbase, const __nv_bfloat16* Ah, const __nv_bfloat16* Al,
    const __nv_bfloat16* Bh, const __nv_bfloat16* Bl,
    int K, int m0, int n0, int k0, int bn, int tid)
{
    ld_tile_async(sbase + 0*TOFF, Ah, K, m0, k0, 128, tid);
    ld_tile_async(sbase + 1*TOFF, Al, K, m0, k0, 128, tid);
    ld_tile_async(sbase + 2*TOFF, Bh, K, n0, k0, bn, tid);
    ld_tile_async(sbase + 3*TOFF, Bl, K, n0, k0, bn, tid);
}

__global__ __launch_bounds__(256) void gemm_tc(
    float* __restrict__ C,
    const __nv_bfloat16* __restrict__ Ah, const __nv_bfloat16* __restrict__ Al,
    const __nv_bfloat16* __restrict__ Bh, const __nv_bfloat16* __restrict__ Bl,
    const float* __restrict__ bias, int M, int N, int K, float alpha, int relu)
{
    extern __shared__ char sm[];
    uint32_t smb = smem_u32(sm);
    int tid = threadIdx.x;
    int wid = tid >> 5;
    int lane = tid & 31;
    int wm = wid & 1;          // 2 warps along M
    int wn = wid >> 1;         // 4 warps along N
    int m0 = blockIdx.y * 128;
    int n0 = blockIdx.x * 128;
    int NT = K >> 5;
    int bn = N - n0; if (bn > 128) bn = 128;

    // prologue: stages 0,1 into slots 0,1
    ld_stage(smb, Ah, Al, Bh, Bl, K, m0, n0, 0, bn, tid);
    CP_COMMIT();
    if (NT > 1) {
        ld_stage(smb + STG, Ah, Al, Bh, Bl, K, m0, n0, 32, bn, tid);
        CP_COMMIT();
    }

    float acc[4][4][4];
    #pragma unroll
    for (int i = 0; i < 4; i++)
        #pragma unroll
        for (int j = 0; j < 4; j++)
            #pragma unroll
            for (int e = 0; e < 4; e++) acc[i][j][e] = 0.f;

    int slot = 0;       // slot of k-tile kt
    int pslot = 2;      // slot where k-tile kt+2 goes
    for (int kt = 0; kt < NT; kt++) {
        if (kt + 1 < NT) { CP_WAIT1(); } else { CP_WAIT0(); }
        __syncthreads();

        // issue loads for kt+2 into the slot freed by iteration kt-1
        if (kt + 2 < NT) {
            ld_stage(smb + pslot * STG, Ah, Al, Bh, Bl, K, m0, n0, (kt + 2) << 5, bn, tid);
            CP_COMMIT();
        }

        uint32_t sA = smb + slot * STG;
        uint32_t sB = sA + 2*TOFF;

        #pragma unroll
        for (int ks = 0; ks < 2; ks++) {
            uint32_t ah[4][4], al[4][4], bh[4][2], bl[4][2];
            #pragma unroll
            for (int mf = 0; mf < 4; mf++) {
                int row = wm * 64 + mf * 16 + (lane & 15);
                int cc = ks * 2 + (lane >> 4);
                uint32_t ad = sA + row * 64 + (((cc ^ ((row >> 1) & 3))) << 4);
                LDSM4(ah[mf], ad);
                LDSM4(al[mf], ad + TOFF);
            }
            #pragma unroll
            for (int nf = 0; nf < 4; nf++) {
                int rn = wn * 32 + nf * 8 + (lane & 7);
                int cc = ks * 2 + ((lane >> 3) & 1);
                uint32_t bd = sB + rn * 64 + (((cc ^ ((rn >> 1) & 3))) << 4);
                LDSM2(bh[nf], bd);
                LDSM2(bl[nf], bd + TOFF);
            }
            // term-major: 16 independent MMAs per term (no same-acc back-to-back)
            #pragma unroll
            for (int mf = 0; mf < 4; mf++)
                #pragma unroll
                for (int nf = 0; nf < 4; nf++)
                    MMA16816(acc[mf][nf], ah[mf], bh[nf]);
            #pragma unroll
            for (int mf = 0; mf < 4; mf++)
                #pragma unroll
                for (int nf = 0; nf < 4; nf++)
                    MMA16816(acc[mf][nf], ah[mf], bl[nf]);
            #pragma unroll
            for (int mf = 0; mf < 4; mf++)
                #pragma unroll
                for (int nf = 0; nf < 4; nf++)
                    MMA16816(acc[mf][nf], al[mf], bh[nf]);
        }
        slot = (slot == 2) ? 0 : slot + 1;
        pslot = (pslot == 2) ? 0 : pslot + 1;
    }

    // epilogue
    bool fast = ((N & 1) == 0) && (n0 + 128 <= N);
    #pragma unroll
    for (int mf = 0; mf < 4; mf++) {
        int r0 = m0 + wm * 64 + mf * 16 + (lane >> 2);
        #pragma unroll
        for (int half = 0; half < 2; half++) {
            int row = r0 + half * 8;
            float* crow = C + (size_t)row * N;
            #pragma unroll
            for (int nf = 0; nf < 4; nf++) {
                int col = n0 + wn * 32 + nf * 8 + (lane & 3) * 2;
                float v0 = acc[mf][nf][half * 2 + 0];
                float v1 = acc[mf][nf][half * 2 + 1];
                if (bias) { v0 += bias[col]; v1 += __ldg(&bias[col + 1]); }
                v0 *= alpha; v1 *= alpha;
                if (relu) { v0 = fmaxf(v0, 0.f); v1 = fmaxf(v1, 0.f); }
                if (fast) {
                    *reinterpret_cast<float2*>(crow + col) = make_float2(v0, v1);
                } else {
                    if (col < N)     crow[col] = v0;
                    if (col + 1 < N) crow[col + 1] = v1;
                }
            }
        }
    }
}

// ---------------- fused attention (flash-style, exact softmax semantics) ----------------
#define QT 128
#define KT 64
#define LDQ 68

__global__ __launch_bounds__(128, 2) void attn_kernel(
    float* __restrict__ out, const float* __restrict__ q, const float* __restrict__ k,
    const float* __restrict__ v, const float* __restrict__ qr, const int* __restrict__ tgt)
{
    extern __shared__ float smf[];
    float* qs = smf;
    float* ks = qs + QT*LDQ;
    float* vs = ks + KT*LDQ;
    float* ps = vs + KT*LDQ;
    int*   pf = (int*)(ps + QT*LDQ);

    int b = blockIdx.z, h = blockIdx.y;
    int tid = threadIdx.x;
    int i0 = blockIdx.x * QT;
    int i  = i0 + tid;

    for (int t = tid; t < QT*NDH/4; t += 128) {
        int r  = t >> 4;
        int c4 = (t & 15) << 2;
        float4 va = *reinterpret_cast<const float4*>(
            &q[((size_t)(b*NS + i0 + r))*ND + h*NDH + c4]);
        *reinterpret_cast<float4*>(&qs[r*LDQ + c4]) = va;
    }

    float o[NDH];
    #pragma unroll
    for (int d = 0; d < NDH; d++) o[d] = 0.f;
    float m = -1e30f, l = 0.f;
    const float* qrrow = qr + ((size_t)((b*NS + i)*NH + h)) * NR + (1023 - i);

    // Causal tile skipping: for j0 >= i0+QT all scores are -1e9; provided at
    // least one real key is visible (tgt[b][0] != 0 guarantees key 0 is
    // unmasked for every row), exp(-1e9 - m) underflows to exactly 0 in fp32,
    // so skipping those tiles is bit-exact. Degenerate all-padded-prefix case
    // (tgt[b][0]==0) falls back to the full scan.
    int jend = (tgt[b*NS] == 0) ? NS : (i0 + QT);

    for (int j0 = 0; j0 < jend; j0 += KT) {
        __syncthreads();
        for (int t = tid; t < KT*NDH/4; t += 128) {
            int r  = t >> 4;
            int c4 = (t & 15) << 2;
            size_t g = ((size_t)(b*NS + j0 + r))*ND + h*NDH + c4;
            *reinterpret_cast<float4*>(&ks[r*LDQ + c4]) =
                *reinterpret_cast<const float4*>(&k[g]);
            *reinterpret_cast<float4*>(&vs[r*LDQ + c4]) =
                *reinterpret_cast<const float4*>(&v[g]);
        }
        if (tid < KT) pf[tid] = (tgt[b*NS + j0 + tid] == 0) ? 1 : 0;
        __syncthreads();

        float s[KT];
        #pragma unroll
        for (int j = 0; j < KT; j++) s[j] = 0.f;
        #pragma unroll 1
        for (int d = 0; d < NDH; d += 4) {
            float4 qd = *reinterpret_cast<const float4*>(&qs[tid*LDQ + d]);
            #pragma unroll
            for (int j = 0; j < KT; j++) {
                float4 kj = *reinterpret_cast<const float4*>(&ks[j*LDQ + d]);
                s[j] += qd.x*kj.x + qd.y*kj.y + qd.z*kj.z + qd.w*kj.w;
            }
        }
        float mt = m;
        #pragma unroll
        for (int j = 0; j < KT; j++) {
            int jj = j0 + j;
            float val = s[j] + qrrow[jj];
            if (jj > i || pf[j]) val = -1e9f;
            s[j] = val;
            mt = fmaxf(mt, val);
        }
        float corr = __expf(m - mt);
        m = mt;
        l *= corr;
        #pragma unroll
        for (int d = 0; d < NDH; d++) o[d] *= corr;
        #pragma unroll
        for (int j = 0; j < KT; j += 4) {
            float4 pv;
            pv.x = __expf(s[j]   - m);
            pv.y = __expf(s[j+1] - m);
            pv.z = __expf(s[j+2] - m);
            pv.w = __expf(s[j+3] - m);
            l += pv.x + pv.y + pv.z + pv.w;
            *reinterpret_cast<float4*>(&ps[tid*LDQ + j]) = pv;
        }
        #pragma unroll 1
        for (int j = 0; j < KT; j++) {
            float p = ps[tid*LDQ + j];
            #pragma unroll
            for (int d = 0; d < NDH; d += 4) {
                float4 vj = *reinterpret_cast<const float4*>(&vs[j*LDQ + d]);
                o[d]   += p*vj.x;
                o[d+1] += p*vj.y;
                o[d+2] += p*vj.z;
                o[d+3] += p*vj.w;
            }
        }
    }
    float inv = 1.f / l;
    #pragma unroll
    for (int d = 0; d < NDH; d += 4) {
        float4 w;
        w.x = o[d]*inv; w.y = o[d+1]*inv; w.z = o[d+2]*inv; w.w = o[d+3]*inv;
        *reinterpret_cast<float4*>(&out[((size_t)(b*NS + i))*ND + h*NDH + d]) = w;
    }
}

// ---------------- residual add + LayerNorm (in place on x) ----------------
__global__ __launch_bounds__(256) void add_ln_kernel(
    float* __restrict__ x, const float* __restrict__ y,
    const float* __restrict__ gw, const float* __restrict__ bw)
{
    __shared__ float buf[ND];
    __shared__ float red[33];
    int row = blockIdx.x;
    int tid = threadIdx.x;
    size_t base = (size_t)row * ND;

    float s = 0.f;
    for (int d = tid; d < ND; d += 256) {
        float t = x[base + d] + y[base + d];
        buf[d] = t;
        s += t;
    }
    #pragma unroll
    for (int off = 16; off; off >>= 1) s += __shfl_xor_sync(0xffffffffu, s, off);
    if ((tid & 31) == 0) red[tid >> 5] = s;
    __syncthreads();
    if (tid < 32) {
        float v2 = (tid < 8) ? red[tid] : 0.f;
        #pragma unroll
        for (int off = 4; off; off >>= 1) v2 += __shfl_xor_sync(0xffffffffu, v2, off);
        if (tid == 0) red[32] = v2;
    }
    __syncthreads();
    float mean = red[32] * (1.f/ND);

    float sv = 0.f;
    for (int d = tid; d < ND; d += 256) {
        float t = buf[d] - mean;
        sv += t*t;
    }
    #pragma unroll
    for (int off = 16; off; off >>= 1) sv += __shfl_xor_sync(0xffffffffu, sv, off);
    __syncthreads();
    if ((tid & 31) == 0) red[tid >> 5] = sv;
    __syncthreads();
    if (tid < 32) {
        float v2 = (tid < 8) ? red[tid] : 0.f;
        #pragma unroll
        for (int off = 4; off; off >>= 1) v2 += __shfl_xor_sync(0xffffffffu, v2, off);
        if (tid == 0) red[32] = v2;
    }
    __syncthreads();
    float inv = rsqrtf(red[32] * (1.f/ND) + 1e-5f);
    for (int d = tid; d < ND; d += 256)
        x[base + d] = (buf[d] - mean) * inv * gw[d] + bw[d];
}

// ---------------- host orchestration ----------------
static inline void split(const float* src, __nv_bfloat16* hi, __nv_bfloat16* lo, size_t n) {
    int n4 = (int)(n / 4);
    split_kernel<<<(n4 + 255) / 256, 256>>>(
        reinterpret_cast<const float4*>(src), hi, lo, n4);
}

extern "C" void kernel_launch(void* const* d_in, const int* in_sizes, int n_in,
                              void* d_out, int out_size)
{
    (void)in_sizes; (void)n_in; (void)out_size;
    const int*   tgt = (const int*)d_in[0];
    const float* emb = (const float*)d_in[1];
    const float* Wq  = (const float*)d_in[2];
    const float* bq  = (const float*)d_in[3];
    const float* Wk  = (const float*)d_in[4];
    const float* bk  = (const float*)d_in[5];
    const float* Wv  = (const float*)d_in[6];
    const float* bv  = (const float*)d_in[7];
    const float* Wo  = (const float*)d_in[8];
    const float* bo  = (const float*)d_in[9];
    const float* rel = (const float*)d_in[10];
    const float* W1  = (const float*)d_in[11];
    const float* b1  = (const float*)d_in[12];
    const float* W2  = (const float*)d_in[13];
    const float* b2  = (const float*)d_in[14];
    const float* g1  = (const float*)d_in[15];
    const float* be1 = (const float*)d_in[16];
    const float* g2  = (const float*)d_in[17];
    const float* be2 = (const float*)d_in[18];
    const float* Wf  = (const float*)d_in[19];
    const float* bf  = (const float*)d_in[20];
    float* logits = (float*)d_out;

    float *x_, *q_, *k_, *v_, *o_, *t_, *h_, *qr_;
    __nv_bfloat16 *Ah, *Al, *Bh, *Bl;
    cudaGetSymbolAddress((void**)&x_,  g_x);
    cudaGetSymbolAddress((void**)&q_,  g_q);
    cudaGetSymbolAddress((void**)&k_,  g_k);
    cudaGetSymbolAddress((void**)&v_,  g_v);
    cudaGetSymbolAddress((void**)&o_,  g_o);
    cudaGetSymbolAddress((void**)&t_,  g_t);
    cudaGetSymbolAddress((void**)&h_,  g_h);
    cudaGetSymbolAddress((void**)&qr_, g_qr);
    cudaGetSymbolAddress((void**)&Ah,  g_Ah);
    cudaGetSymbolAddress((void**)&Al,  g_Al);
    cudaGetSymbolAddress((void**)&Bh,  g_Bh);
    cudaGetSymbolAddress((void**)&Bl,  g_Bl);

    int attn_smem = (QT*LDQ + KT*LDQ + KT*LDQ + QT*LDQ)*(int)sizeof(float) + KT*(int)sizeof(int);
    cudaFuncSetAttribute(attn_kernel, cudaFuncAttributeMaxDynamicSharedMemorySize, attn_smem);
    cudaFuncSetAttribute(gemm_tc, cudaFuncAttributeMaxDynamicSharedMemorySize, GEMM_SMEM);

    embed_kernel<<<NROWS*ND/4/256, 256>>>(tgt, emb, x_);

    for (int l = 0; l < NL; l++) {
        const size_t WDD = (size_t)ND*ND;
        // q/k/v projections
        split(x_, Ah, Al, (size_t)NROWS*ND);
        split(Wq + l*WDD, Bh, Bl, WDD);
        gemm_tc<<<dim3(ND/128, NROWS/128), 256, GEMM_SMEM>>>(
            q_, Ah, Al, Bh, Bl, bq + l*ND, NROWS, ND, ND, 0.125f, 0);
        split(Wk + l*WDD, Bh, Bl, WDD);
        gemm_tc<<<dim3(ND/128, NROWS/128), 256, GEMM_SMEM>>>(
            k_, Ah, Al, Bh, Bl, bk + l*ND, NROWS, ND, ND, 1.f, 0);
        split(Wv + l*WDD, Bh, Bl, WDD);
        gemm_tc<<<dim3(ND/128, NROWS/128), 256, GEMM_SMEM>>>(
            v_, Ah, Al, Bh, Bl, bv + l*ND, NROWS, ND, ND, 1.f, 0);

        // QR[bsh, r] = q . rel^T : M=32768, N=2047, K=64
        split(q_, Ah, Al, (size_t)NROWS*ND);
        split(rel + (size_t)l*NR*NDH, Bh, Bl, (size_t)NR*NDH);
        gemm_tc<<<dim3((NR + 127)/128, NROWS*NH/128), 256, GEMM_SMEM>>>(
            qr_, Ah, Al, Bh, Bl, (const float*)nullptr, NROWS*NH, NR, NDH, 1.f, 0);

        attn_kernel<<<dim3(NS/QT, NH, NB), 128, attn_smem>>>(o_, q_, k_, v_, qr_, tgt);

        // output projection + LN
        split(o_, Ah, Al, (size_t)NROWS*ND);
        split(Wo + l*WDD, Bh, Bl, WDD);
        gemm_tc<<<dim3(ND/128, NROWS/128), 256, GEMM_SMEM>>>(
            t_, Ah, Al, Bh, Bl, bo + l*ND, NROWS, ND, ND, 1.f, 0);
        add_ln_kernel<<<NROWS, 256>>>(x_, t_, g1 + l*ND, be1 + l*ND);

        // FFN
        split(x_, Ah, Al, (size_t)NROWS*ND);
        split(W1 + (size_t)l*NDFF*ND, Bh, Bl, (size_t)NDFF*ND);
        gemm_tc<<<dim3(NDFF/128, NROWS/128), 256, GEMM_SMEM>>>(
            h_, Ah, Al, Bh, Bl, b1 + l*NDFF, NROWS, NDFF, ND, 1.f, 1);
        split(h_, Ah, Al, (size_t)NROWS*NDFF);
        split(W2 + (size_t)l*ND*NDFF, Bh, Bl, (size_t)ND*NDFF);
        gemm_tc<<<dim3(ND/128, NROWS/128), 256, GEMM_SMEM>>>(
            t_, Ah, Al, Bh, Bl, b2 + l*ND, NROWS, ND, NDFF, 1.f, 0);
        add_ln_kernel<<<NROWS, 256>>>(x_, t_, g2 + l*ND, be2 + l*ND);
    }

    // final logits: M=2048, N=32000, K=1024
    split(x_, Ah, Al, (size_t)NROWS*ND);
    split(Wf, Bh, Bl, (size_t)NV*ND);
    gemm_tc<<<dim3(NV/128, NROWS/128), 256, GEMM_SMEM>>>(
        logits, Ah, Al, Bh, Bl, bf, NROWS, NV, ND, 1.f, 0);
}

// round 5
// speedup vs baseline: 2.2304x; 1.0794x over previous
#include <cuda_runtime.h>
#include <cuda_bf16.h>
#include <cstdint>
#include <math.h>

// ---------------- problem constants ----------------
#define NB 2
#define NS 1024
#define ND 1024
#define NH 16
#define NDH 64
#define NL 4
#define NDFF 4096
#define NV 32000
#define NR 2047              // 2*MAXLEN-1
#define NROWS (NB*NS)        // 2048

// ---------------- scratch (static device allocations) ----------------
__device__ float g_x[NROWS*ND];
__device__ float g_q[NROWS*ND];
__device__ float g_k[NROWS*ND];
__device__ float g_v[NROWS*ND];
__device__ float g_o[NROWS*ND];
__device__ float g_t[NROWS*ND];
__device__ float g_h[NROWS*NDFF];
__device__ float g_p[2*NROWS*ND];             // split-K partials
__device__ float g_qr[(size_t)NROWS*NH*NR];   // [B*S*H, 2047]

// split-bf16 operand buffers
__device__ __nv_bfloat16 g_Ah[(size_t)NROWS*NDFF];
__device__ __nv_bfloat16 g_Al[(size_t)NROWS*NDFF];
__device__ __nv_bfloat16 g_Bh[(size_t)NV*ND];
__device__ __nv_bfloat16 g_Bl[(size_t)NV*ND];

// ---------------- helpers ----------------
__device__ __forceinline__ uint32_t smem_u32(const void* p) {
    uint32_t a;
    asm("{ .reg .u64 t; cvta.to.shared.u64 t, %1; cvt.u32.u64 %0, t; }" : "=r"(a) : "l"(p));
    return a;
}

#define LDSM4(r, a) \
    asm volatile("ldmatrix.sync.aligned.m8n8.x4.shared.b16 {%0,%1,%2,%3}, [%4];" \
        : "=r"((r)[0]), "=r"((r)[1]), "=r"((r)[2]), "=r"((r)[3]) : "r"(a))
#define LDSM2(r, a) \
    asm volatile("ldmatrix.sync.aligned.m8n8.x2.shared.b16 {%0,%1}, [%2];" \
        : "=r"((r)[0]), "=r"((r)[1]) : "r"(a))

#define MMA16816(d, a, b) \
    asm volatile("mma.sync.aligned.m16n8k16.row.col.f32.bf16.bf16.f32 " \
        "{%0,%1,%2,%3}, {%4,%5,%6,%7}, {%8,%9}, {%0,%1,%2,%3};" \
        : "+f"((d)[0]), "+f"((d)[1]), "+f"((d)[2]), "+f"((d)[3]) \
        : "r"((a)[0]), "r"((a)[1]), "r"((a)[2]), "r"((a)[3]), "r"((b)[0]), "r"((b)[1]))

#define CP_ASYNC16(dst, src, sz) \
    asm volatile("cp.async.cg.shared.global [%0], [%1], 16, %2;" \
        :: "r"(dst), "l"(src), "r"(sz))
#define CP_COMMIT() asm volatile("cp.async.commit_group;")
#define CP_WAIT0()  asm volatile("cp.async.wait_group 0;")
#define CP_WAIT1()  asm volatile("cp.async.wait_group 1;")

// ---------------- fp32 -> bf16 hi/lo split ----------------
__global__ void split_kernel(const float4* __restrict__ src,
                             __nv_bfloat16* __restrict__ hi,
                             __nv_bfloat16* __restrict__ lo, int n4) {
    int i = blockIdx.x * 256 + threadIdx.x;
    if (i >= n4) return;
    float4 v = src[i];
    __nv_bfloat16 h0 = __float2bfloat16(v.x);
    __nv_bfloat16 h1 = __float2bfloat16(v.y);
    __nv_bfloat16 h2 = __float2bfloat16(v.z);
    __nv_bfloat16 h3 = __float2bfloat16(v.w);
    __nv_bfloat16 l0 = __float2bfloat16(v.x - __bfloat162float(h0));
    __nv_bfloat16 l1 = __float2bfloat16(v.y - __bfloat162float(h1));
    __nv_bfloat16 l2 = __float2bfloat16(v.z - __bfloat162float(h2));
    __nv_bfloat16 l3 = __float2bfloat16(v.w - __bfloat162float(h3));
    __nv_bfloat162* H = reinterpret_cast<__nv_bfloat162*>(hi);
    __nv_bfloat162* L = reinterpret_cast<__nv_bfloat162*>(lo);
    H[i*2+0] = __nv_bfloat162(h0, h1);
    H[i*2+1] = __nv_bfloat162(h2, h3);
    L[i*2+0] = __nv_bfloat162(l0, l1);
    L[i*2+1] = __nv_bfloat162(l2, l3);
}

// ---------------- embedding: x = emb[tgt] * sqrt(D) ----------------
__global__ void embed_kernel(const int* __restrict__ tgt,
                             const float* __restrict__ emb,
                             float* __restrict__ x) {
    int idx = blockIdx.x * blockDim.x + threadIdx.x;
    int row = idx >> 8;
    int c4  = idx & 255;
    float4 v = reinterpret_cast<const float4*>(emb + (size_t)tgt[row] * ND)[c4];
    v.x *= 32.f; v.y *= 32.f; v.z *= 32.f; v.w *= 32.f;
    reinterpret_cast<float4*>(x)[idx] = v;
}

// ---------------- split-K reduce: out = relu(alpha*(P0+P1+bias)) ----------------
__global__ __launch_bounds__(256) void reduce2_kernel(
    float* __restrict__ out, const float* __restrict__ P,
    const float* __restrict__ bias, int N, int total4, float alpha, int relu)
{
    int idx = blockIdx.x * 256 + threadIdx.x;
    if (idx >= total4) return;
    const float4* P0 = reinterpret_cast<const float4*>(P);
    const float4* P1 = P0 + total4;
    float4 a = P0[idx], b = P1[idx];
    int col = (idx << 2) & (N - 1);          // N is a power of two here
    float4 bz = *reinterpret_cast<const float4*>(bias + col);
    float4 o;
    o.x = (a.x + b.x + bz.x) * alpha;
    o.y = (a.y + b.y + bz.y) * alpha;
    o.z = (a.z + b.z + bz.z) * alpha;
    o.w = (a.w + b.w + bz.w) * alpha;
    if (relu) {
        o.x = fmaxf(o.x, 0.f); o.y = fmaxf(o.y, 0.f);
        o.z = fmaxf(o.z, 0.f); o.w = fmaxf(o.w, 0.f);
    }
    reinterpret_cast<float4*>(out)[idx] = o;
}

// ---------------- split-bf16 tensor-core GEMM (mma.sync) ----------------
// C[M,N] (+z-slice) = alpha*((Ahi+Alo)[M,K]@(Bhi+Blo)[N,K]^T + bias), opt relu.
// CTA tile 128x128, k-tile 32, 8 warps (2x4), warp 64x32, 3-stage pipeline.
// gridDim.z = split-K count; slice z covers k in [z*K, (z+1)*K) of row stride ldk
// and writes C + z*M*N.
#define STG 32768
#define TOFF 8192
#define GEMM_SMEM (3*STG)

__device__ __forceinline__ void ld_tile_async(
    uint32_t sbase, const __nv_bfloat16* __restrict__ g,
    int ldk, int row0, int k0, int rmax, int tid)
{
    #pragma unroll
    for (int it = 0; it < 2; it++) {
        int qq = tid + it * 256;
        int r = qq >> 2, c = qq & 3;
        uint32_t dst = sbase + r * 64 + ((c ^ ((r >> 1) & 3)) << 4);
        int rr = (r < rmax) ? r : 0;
        const __nv_bfloat16* src = g + (size_t)(row0 + rr) * ldk + k0 + c * 8;
        int sz = (r < rmax) ? 16 : 0;
        CP_ASYNC16(dst, src, sz);
    }
}

__device__ __forceinline__ void ld_stage(
    uint32_t sbase, const __nv_bfloat16* Ah, const __nv_bfloat16* Al,
    const __nv_bfloat16* Bh, const __nv_bfloat16* Bl,
    int ldk, int m0, int n0, int k0, int bn, int tid)
{
    ld_tile_async(sbase + 0*TOFF, Ah, ldk, m0, k0, 128, tid);
    ld_tile_async(sbase + 1*TOFF, Al, ldk, m0, k0, 128, tid);
    ld_tile_async(sbase + 2*TOFF, Bh, ldk, n0, k0, bn, tid);
    ld_tile_async(sbase + 3*TOFF, Bl, ldk, n0, k0, bn, tid);
}

__global__ __launch_bounds__(256, 2) void gemm_tc(
    float* __restrict__ C,
    const __nv_bfloat16* __restrict__ Ah, const __nv_bfloat16* __restrict__ Al,
    const __nv_bfloat16* __restrict__ Bh, const __nv_bfloat16* __restrict__ Bl,
    const float* __restrict__ bias, int M, int N, int K, int ldk,
    float alpha, int relu)
{
    extern __shared__ char sm[];
    uint32_t smb = smem_u32(sm);
    int tid = threadIdx.x;
    int wid = tid >> 5;
    int lane = tid & 31;
    int wm = wid & 1;          // 2 warps along M
    int wn = wid >> 1;         // 4 warps along N
    int m0 = blockIdx.y * 128;
    int n0 = blockIdx.x * 128;
    int kbase = blockIdx.z * K;
    C += (size_t)blockIdx.z * M * N;
    int NT = K >> 5;
    int bn = N - n0; if (bn > 128) bn = 128;

    // prologue: stages 0,1 into slots 0,1
    ld_stage(smb, Ah, Al, Bh, Bl, ldk, m0, n0, kbase, bn, tid);
    CP_COMMIT();
    if (NT > 1) {
        ld_stage(smb + STG, Ah, Al, Bh, Bl, ldk, m0, n0, kbase + 32, bn, tid);
        CP_COMMIT();
    }

    float acc[4][4][4];
    #pragma unroll
    for (int i = 0; i < 4; i++)
        #pragma unroll
        for (int j = 0; j < 4; j++)
            #pragma unroll
            for (int e = 0; e < 4; e++) acc[i][j][e] = 0.f;

    int slot = 0;       // slot of k-tile kt
    int pslot = 2;      // slot where k-tile kt+2 goes
    for (int kt = 0; kt < NT; kt++) {
        if (kt + 1 < NT) { CP_WAIT1(); } else { CP_WAIT0(); }
        __syncthreads();

        // issue loads for kt+2 into the slot freed by iteration kt-1
        if (kt + 2 < NT) {
            ld_stage(smb + pslot * STG, Ah, Al, Bh, Bl, ldk, m0, n0,
                     kbase + ((kt + 2) << 5), bn, tid);
            CP_COMMIT();
        }

        uint32_t sA = smb + slot * STG;
        uint32_t sB = sA + 2*TOFF;

        #pragma unroll
        for (int ks = 0; ks < 2; ks++) {
            uint32_t ah[4][4], al[4][4], bh[4][2], bl[4][2];
            #pragma unroll
            for (int mf = 0; mf < 4; mf++) {
                int row = wm * 64 + mf * 16 + (lane & 15);
                int cc = ks * 2 + (lane >> 4);
                uint32_t ad = sA + row * 64 + (((cc ^ ((row >> 1) & 3))) << 4);
                LDSM4(ah[mf], ad);
                LDSM4(al[mf], ad + TOFF);
            }
            #pragma unroll
            for (int nf = 0; nf < 4; nf++) {
                int rn = wn * 32 + nf * 8 + (lane & 7);
                int cc = ks * 2 + ((lane >> 3) & 1);
                uint32_t bd = sB + rn * 64 + (((cc ^ ((rn >> 1) & 3))) << 4);
                LDSM2(bh[nf], bd);
                LDSM2(bl[nf], bd + TOFF);
            }
            // term-major: 16 independent MMAs per term
            #pragma unroll
            for (int mf = 0; mf < 4; mf++)
                #pragma unroll
                for (int nf = 0; nf < 4; nf++)
                    MMA16816(acc[mf][nf], ah[mf], bh[nf]);
            #pragma unroll
            for (int mf = 0; mf < 4; mf++)
                #pragma unroll
                for (int nf = 0; nf < 4; nf++)
                    MMA16816(acc[mf][nf], ah[mf], bl[nf]);
            #pragma unroll
            for (int mf = 0; mf < 4; mf++)
                #pragma unroll
                for (int nf = 0; nf < 4; nf++)
                    MMA16816(acc[mf][nf], al[mf], bh[nf]);
        }
        slot = (slot == 2) ? 0 : slot + 1;
        pslot = (pslot == 2) ? 0 : pslot + 1;
    }

    // epilogue
    bool fast = ((N & 1) == 0) && (n0 + 128 <= N);
    #pragma unroll
    for (int mf = 0; mf < 4; mf++) {
        int r0 = m0 + wm * 64 + mf * 16 + (lane >> 2);
        #pragma unroll
        for (int half = 0; half < 2; half++) {
            int row = r0 + half * 8;
            float* crow = C + (size_t)row * N;
            #pragma unroll
            for (int nf = 0; nf < 4; nf++) {
                int col = n0 + wn * 32 + nf * 8 + (lane & 3) * 2;
                float v0 = acc[mf][nf][half * 2 + 0];
                float v1 = acc[mf][nf][half * 2 + 1];
                if (bias) { v0 += bias[col]; v1 += __ldg(&bias[col + 1]); }
                v0 *= alpha; v1 *= alpha;
                if (relu) { v0 = fmaxf(v0, 0.f); v1 = fmaxf(v1, 0.f); }
                if (fast) {
                    *reinterpret_cast<float2*>(crow + col) = make_float2(v0, v1);
                } else {
                    if (col < N)     crow[col] = v0;
                    if (col + 1 < N) crow[col + 1] = v1;
                }
            }
        }
    }
}

// ---------------- fused attention (flash-style, exact softmax semantics) ----------------
#define QT 128
#define KT 64
#define LDQ 68

__global__ __launch_bounds__(128, 2) void attn_kernel(
    float* __restrict__ out, const float* __restrict__ q, const float* __restrict__ k,
    const float* __restrict__ v, const float* __restrict__ qr, const int* __restrict__ tgt)
{
    extern __shared__ float smf[];
    float* qs = smf;
    float* ks = qs + QT*LDQ;
    float* vs = ks + KT*LDQ;
    float* ps = vs + KT*LDQ;
    int*   pf = (int*)(ps + QT*LDQ);

    int b = blockIdx.z, h = blockIdx.y;
    int tid = threadIdx.x;
    int i0 = blockIdx.x * QT;
    int i  = i0 + tid;

    for (int t = tid; t < QT*NDH/4; t += 128) {
        int r  = t >> 4;
        int c4 = (t & 15) << 2;
        float4 va = *reinterpret_cast<const float4*>(
            &q[((size_t)(b*NS + i0 + r))*ND + h*NDH + c4]);
        *reinterpret_cast<float4*>(&qs[r*LDQ + c4]) = va;
    }

    float o[NDH];
    #pragma unroll
    for (int d = 0; d < NDH; d++) o[d] = 0.f;
    float m = -1e30f, l = 0.f;
    const float* qrrow = qr + ((size_t)((b*NS + i)*NH + h)) * NR + (1023 - i);

    // Causal tile skipping (bit-exact when key 0 is unmasked; see R4 notes).
    int jend = (tgt[b*NS] == 0) ? NS : (i0 + QT);

    for (int j0 = 0; j0 < jend; j0 += KT) {
        __syncthreads();
        for (int t = tid; t < KT*NDH/4; t += 128) {
            int r  = t >> 4;
            int c4 = (t & 15) << 2;
            size_t g = ((size_t)(b*NS + j0 + r))*ND + h*NDH + c4;
            *reinterpret_cast<float4*>(&ks[r*LDQ + c4]) =
                *reinterpret_cast<const float4*>(&k[g]);
            *reinterpret_cast<float4*>(&vs[r*LDQ + c4]) =
                *reinterpret_cast<const float4*>(&v[g]);
        }
        if (tid < KT) pf[tid] = (tgt[b*NS + j0 + tid] == 0) ? 1 : 0;
        __syncthreads();

        float s[KT];
        #pragma unroll
        for (int j = 0; j < KT; j++) s[j] = 0.f;
        #pragma unroll 1
        for (int d = 0; d < NDH; d += 4) {
            float4 qd = *reinterpret_cast<const float4*>(&qs[tid*LDQ + d]);
            #pragma unroll
            for (int j = 0; j < KT; j++) {
                float4 kj = *reinterpret_cast<const float4*>(&ks[j*LDQ + d]);
                s[j] += qd.x*kj.x + qd.y*kj.y + qd.z*kj.z + qd.w*kj.w;
            }
        }
        float mt = m;
        #pragma unroll
        for (int j = 0; j < KT; j++) {
            int jj = j0 + j;
            float val = s[j] + qrrow[jj];
            if (jj > i || pf[j]) val = -1e9f;
            s[j] = val;
            mt = fmaxf(mt, val);
        }
        float corr = __expf(m - mt);
        m = mt;
        l *= corr;
        #pragma unroll
        for (int d = 0; d < NDH; d++) o[d] *= corr;
        #pragma unroll
        for (int j = 0; j < KT; j += 4) {
            float4 pv;
            pv.x = __expf(s[j]   - m);
            pv.y = __expf(s[j+1] - m);
            pv.z = __expf(s[j+2] - m);
            pv.w = __expf(s[j+3] - m);
            l += pv.x + pv.y + pv.z + pv.w;
            *reinterpret_cast<float4*>(&ps[tid*LDQ + j]) = pv;
        }
        #pragma unroll 1
        for (int j = 0; j < KT; j++) {
            float p = ps[tid*LDQ + j];
            #pragma unroll
            for (int d = 0; d < NDH; d += 4) {
                float4 vj = *reinterpret_cast<const float4*>(&vs[j*LDQ + d]);
                o[d]   += p*vj.x;
                o[d+1] += p*vj.y;
                o[d+2] += p*vj.z;
                o[d+3] += p*vj.w;
            }
        }
    }
    float inv = 1.f / l;
    #pragma unroll
    for (int d = 0; d < NDH; d += 4) {
        float4 w;
        w.x = o[d]*inv; w.y = o[d+1]*inv; w.z = o[d+2]*inv; w.w = o[d+3]*inv;
        *reinterpret_cast<float4*>(&out[((size_t)(b*NS + i))*ND + h*NDH + d]) = w;
    }
}

// ---------------- residual add + LayerNorm (in place on x) ----------------
__global__ __launch_bounds__(256) void add_ln_kernel(
    float* __restrict__ x, const float* __restrict__ y,
    const float* __restrict__ gw, const float* __restrict__ bw)
{
    __shared__ float buf[ND];
    __shared__ float red[33];
    int row = blockIdx.x;
    int tid = threadIdx.x;
    size_t base = (size_t)row * ND;

    float s = 0.f;
    for (int d = tid; d < ND; d += 256) {
        float t = x[base + d] + y[base + d];
        buf[d] = t;
        s += t;
    }
    #pragma unroll
    for (int off = 16; off; off >>= 1) s += __shfl_xor_sync(0xffffffffu, s, off);
    if ((tid & 31) == 0) red[tid >> 5] = s;
    __syncthreads();
    if (tid < 32) {
        float v2 = (tid < 8) ? red[tid] : 0.f;
        #pragma unroll
        for (int off = 4; off; off >>= 1) v2 += __shfl_xor_sync(0xffffffffu, v2, off);
        if (tid == 0) red[32] = v2;
    }
    __syncthreads();
    float mean = red[32] * (1.f/ND);

    float sv = 0.f;
    for (int d = tid; d < ND; d += 256) {
        float t = buf[d] - mean;
        sv += t*t;
    }
    #pragma unroll
    for (int off = 16; off; off >>= 1) sv += __shfl_xor_sync(0xffffffffu, sv, off);
    __syncthreads();
    if ((tid & 31) == 0) red[tid >> 5] = sv;
    __syncthreads();
    if (tid < 32) {
        float v2 = (tid < 8) ? red[tid] : 0.f;
        #pragma unroll
        for (int off = 4; off; off >>= 1) v2 += __shfl_xor_sync(0xffffffffu, v2, off);
        if (tid == 0) red[32] = v2;
    }
    __syncthreads();
    float inv = rsqrtf(red[32] * (1.f/ND) + 1e-5f);
    for (int d = tid; d < ND; d += 256)
        x[base + d] = (buf[d] - mean) * inv * gw[d] + bw[d];
}

// ---------------- host orchestration ----------------
static inline void split(const float* src, __nv_bfloat16* hi, __nv_bfloat16* lo, size_t n) {
    int n4 = (int)(n / 4);
    split_kernel<<<(n4 + 255) / 256, 256>>>(
        reinterpret_cast<const float4*>(src), hi, lo, n4);
}

extern "C" void kernel_launch(void* const* d_in, const int* in_sizes, int n_in,
                              void* d_out, int out_size)
{
    (void)in_sizes; (void)n_in; (void)out_size;
    const int*   tgt = (const int*)d_in[0];
    const float* emb = (const float*)d_in[1];
    const float* Wq  = (const float*)d_in[2];
    const float* bq  = (const float*)d_in[3];
    const float* Wk  = (const float*)d_in[4];
    const float* bk  = (const float*)d_in[5];
    const float* Wv  = (const float*)d_in[6];
    const float* bv  = (const float*)d_in[7];
    const float* Wo  = (const float*)d_in[8];
    const float* bo  = (const float*)d_in[9];
    const float* rel = (const float*)d_in[10];
    const float* W1  = (const float*)d_in[11];
    const float* b1  = (const float*)d_in[12];
    const float* W2  = (const float*)d_in[13];
    const float* b2  = (const float*)d_in[14];
    const float* g1  = (const float*)d_in[15];
    const float* be1 = (const float*)d_in[16];
    const float* g2  = (const float*)d_in[17];
    const float* be2 = (const float*)d_in[18];
    const float* Wf  = (const float*)d_in[19];
    const float* bf  = (const float*)d_in[20];
    float* logits = (float*)d_out;

    float *x_, *q_, *k_, *v_, *o_, *t_, *h_, *p_, *qr_;
    __nv_bfloat16 *Ah, *Al, *Bh, *Bl;
    cudaGetSymbolAddress((void**)&x_,  g_x);
    cudaGetSymbolAddress((void**)&q_,  g_q);
    cudaGetSymbolAddress((void**)&k_,  g_k);
    cudaGetSymbolAddress((void**)&v_,  g_v);
    cudaGetSymbolAddress((void**)&o_,  g_o);
    cudaGetSymbolAddress((void**)&t_,  g_t);
    cudaGetSymbolAddress((void**)&h_,  g_h);
    cudaGetSymbolAddress((void**)&p_,  g_p);
    cudaGetSymbolAddress((void**)&qr_, g_qr);
    cudaGetSymbolAddress((void**)&Ah,  g_Ah);
    cudaGetSymbolAddress((void**)&Al,  g_Al);
    cudaGetSymbolAddress((void**)&Bh,  g_Bh);
    cudaGetSymbolAddress((void**)&Bl,  g_Bl);

    int attn_smem = (QT*LDQ + KT*LDQ + KT*LDQ + QT*LDQ)*(int)sizeof(float) + KT*(int)sizeof(int);
    cudaFuncSetAttribute(attn_kernel, cudaFuncAttributeMaxDynamicSharedMemorySize, attn_smem);
    cudaFuncSetAttribute(gemm_tc, cudaFuncAttributeMaxDynamicSharedMemorySize, GEMM_SMEM);

    embed_kernel<<<NROWS*ND/4/256, 256>>>(tgt, emb, x_);

    const int RED4 = NROWS*ND/4;            // reduce elements (float4)
    const dim3 gRED((RED4 + 255)/256);

    for (int l = 0; l < NL; l++) {
        const size_t WDD = (size_t)ND*ND;
        // q/k/v projections: split-K=2 (K=512 each half, ldk=1024)
        split(x_, Ah, Al, (size_t)NROWS*ND);
        split(Wq + l*WDD, Bh, Bl, WDD);
        gemm_tc<<<dim3(ND/128, NROWS/128, 2), 256, GEMM_SMEM>>>(
            p_, Ah, Al, Bh, Bl, nullptr, NROWS, ND, 512, ND, 1.f, 0);
        reduce2_kernel<<<gRED, 256>>>(q_, p_, bq + l*ND, ND, RED4, 0.125f, 0);
        split(Wk + l*WDD, Bh, Bl, WDD);
        gemm_tc<<<dim3(ND/128, NROWS/128, 2), 256, GEMM_SMEM>>>(
            p_, Ah, Al, Bh, Bl, nullptr, NROWS, ND, 512, ND, 1.f, 0);
        reduce2_kernel<<<gRED, 256>>>(k_, p_, bk + l*ND, ND, RED4, 1.f, 0);
        split(Wv + l*WDD, Bh, Bl, WDD);
        gemm_tc<<<dim3(ND/128, NROWS/128, 2), 256, GEMM_SMEM>>>(
            p_, Ah, Al, Bh, Bl, nullptr, NROWS, ND, 512, ND, 1.f, 0);
        reduce2_kernel<<<gRED, 256>>>(v_, p_, bv + l*ND, ND, RED4, 1.f, 0);

        // QR[bsh, r] = q . rel^T : M=32768, N=2047, K=64 (grid 4096, no split)
        split(q_, Ah, Al, (size_t)NROWS*ND);
        split(rel + (size_t)l*NR*NDH, Bh, Bl, (size_t)NR*NDH);
        gemm_tc<<<dim3((NR + 127)/128, NROWS*NH/128), 256, GEMM_SMEM>>>(
            qr_, Ah, Al, Bh, Bl, (const float*)nullptr, NROWS*NH, NR, NDH, NDH, 1.f, 0);

        attn_kernel<<<dim3(NS/QT, NH, NB), 128, attn_smem>>>(o_, q_, k_, v_, qr_, tgt);

        // output projection (split-K=2) + LN
        split(o_, Ah, Al, (size_t)NROWS*ND);
        split(Wo + l*WDD, Bh, Bl, WDD);
        gemm_tc<<<dim3(ND/128, NROWS/128, 2), 256, GEMM_SMEM>>>(
            p_, Ah, Al, Bh, Bl, nullptr, NROWS, ND, 512, ND, 1.f, 0);
        reduce2_kernel<<<gRED, 256>>>(t_, p_, bo + l*ND, ND, RED4, 1.f, 0);
        add_ln_kernel<<<NROWS, 256>>>(x_, t_, g1 + l*ND, be1 + l*ND);

        // FFN1 (grid 512, no split)
        split(x_, Ah, Al, (size_t)NROWS*ND);
        split(W1 + (size_t)l*NDFF*ND, Bh, Bl, (size_t)NDFF*ND);
        gemm_tc<<<dim3(NDFF/128, NROWS/128), 256, GEMM_SMEM>>>(
            h_, Ah, Al, Bh, Bl, b1 + l*NDFF, NROWS, NDFF, ND, ND, 1.f, 1);
        // FFN2 (K=4096 -> split-K=2 of 2048)
        split(h_, Ah, Al, (size_t)NROWS*NDFF);
        split(W2 + (size_t)l*ND*NDFF, Bh, Bl, (size_t)ND*NDFF);
        gemm_tc<<<dim3(ND/128, NROWS/128, 2), 256, GEMM_SMEM>>>(
            p_, Ah, Al, Bh, Bl, nullptr, NROWS, ND, 2048, NDFF, 1.f, 0);
        reduce2_kernel<<<gRED, 256>>>(t_, p_, b2 + l*ND, ND, RED4, 1.f, 0);
        add_ln_kernel<<<NROWS, 256>>>(x_, t_, g2 + l*ND, be2 + l*ND);
    }

    // final logits: M=2048, N=32000, K=1024 (grid 4000, no split)
    split(x_, Ah, Al, (size_t)NROWS*ND);
    split(Wf, Bh, Bl, (size_t)NV*ND);
    gemm_tc<<<dim3(NV/128, NROWS/128), 256, GEMM_SMEM>>>(
        logits, Ah, Al, Bh, Bl, bf, NROWS, NV, ND, ND, 1.f, 0);
}

// round 6
// speedup vs baseline: 2.2363x; 1.0026x over previous
#include <cuda_runtime.h>
#include <cuda_bf16.h>
#include <cstdint>
#include <math.h>

// ---------------- problem constants ----------------
#define NB 2
#define NS 1024
#define ND 1024
#define NH 16
#define NDH 64
#define NL 4
#define NDFF 4096
#define NV 32000
#define NR 2047              // 2*MAXLEN-1
#define NROWS (NB*NS)        // 2048

// ---------------- scratch (static device allocations) ----------------
__device__ float g_x[NROWS*ND];
__device__ float g_q[NROWS*ND];
__device__ float g_k[NROWS*ND];
__device__ float g_v[NROWS*ND];
__device__ float g_o[NROWS*ND];
__device__ float g_t[NROWS*ND];
__device__ float g_h[NROWS*NDFF];
__device__ float g_p[2*NROWS*ND];             // split-K partials
__device__ float g_qr[(size_t)NROWS*NH*NR];   // [B*S*H, 2047]

// split-bf16 operand buffers
__device__ __nv_bfloat16 g_Ah[(size_t)NROWS*NDFF];
__device__ __nv_bfloat16 g_Al[(size_t)NROWS*NDFF];
__device__ __nv_bfloat16 g_Bh[(size_t)NV*ND];
__device__ __nv_bfloat16 g_Bl[(size_t)NV*ND];

// ---------------- helpers ----------------
__device__ __forceinline__ uint32_t smem_u32(const void* p) {
    uint32_t a;
    asm("{ .reg .u64 t; cvta.to.shared.u64 t, %1; cvt.u32.u64 %0, t; }" : "=r"(a) : "l"(p));
    return a;
}

#define LDSM4(r, a) \
    asm volatile("ldmatrix.sync.aligned.m8n8.x4.shared.b16 {%0,%1,%2,%3}, [%4];" \
        : "=r"((r)[0]), "=r"((r)[1]), "=r"((r)[2]), "=r"((r)[3]) : "r"(a))
#define LDSM2(r, a) \
    asm volatile("ldmatrix.sync.aligned.m8n8.x2.shared.b16 {%0,%1}, [%2];" \
        : "=r"((r)[0]), "=r"((r)[1]) : "r"(a))

#define MMA16816(d, a, b) \
    asm volatile("mma.sync.aligned.m16n8k16.row.col.f32.bf16.bf16.f32 " \
        "{%0,%1,%2,%3}, {%4,%5,%6,%7}, {%8,%9}, {%0,%1,%2,%3};" \
        : "+f"((d)[0]), "+f"((d)[1]), "+f"((d)[2]), "+f"((d)[3]) \
        : "r"((a)[0]), "r"((a)[1]), "r"((a)[2]), "r"((a)[3]), "r"((b)[0]), "r"((b)[1]))

#define CP_ASYNC16(dst, src, sz) \
    asm volatile("cp.async.cg.shared.global [%0], [%1], 16, %2;" \
        :: "r"(dst), "l"(src), "r"(sz))
#define CP_COMMIT() asm volatile("cp.async.commit_group;")
#define CP_WAIT0()  asm volatile("cp.async.wait_group 0;")
#define CP_WAIT1()  asm volatile("cp.async.wait_group 1;")

// ---------------- fp32 -> bf16 hi/lo split ----------------
__global__ void split_kernel(const float4* __restrict__ src,
                             __nv_bfloat16* __restrict__ hi,
                             __nv_bfloat16* __restrict__ lo, int n4) {
    int i = blockIdx.x * 256 + threadIdx.x;
    if (i >= n4) return;
    float4 v = src[i];
    __nv_bfloat16 h0 = __float2bfloat16(v.x);
    __nv_bfloat16 h1 = __float2bfloat16(v.y);
    __nv_bfloat16 h2 = __float2bfloat16(v.z);
    __nv_bfloat16 h3 = __float2bfloat16(v.w);
    __nv_bfloat16 l0 = __float2bfloat16(v.x - __bfloat162float(h0));
    __nv_bfloat16 l1 = __float2bfloat16(v.y - __bfloat162float(h1));
    __nv_bfloat16 l2 = __float2bfloat16(v.z - __bfloat162float(h2));
    __nv_bfloat16 l3 = __float2bfloat16(v.w - __bfloat162float(h3));
    __nv_bfloat162* H = reinterpret_cast<__nv_bfloat162*>(hi);
    __nv_bfloat162* L = reinterpret_cast<__nv_bfloat162*>(lo);
    H[i*2+0] = __nv_bfloat162(h0, h1);
    H[i*2+1] = __nv_bfloat162(h2, h3);
    L[i*2+0] = __nv_bfloat162(l0, l1);
    L[i*2+1] = __nv_bfloat162(l2, l3);
}

// ---------------- embedding: x = emb[tgt] * sqrt(D) ----------------
__global__ void embed_kernel(const int* __restrict__ tgt,
                             const float* __restrict__ emb,
                             float* __restrict__ x) {
    int idx = blockIdx.x * blockDim.x + threadIdx.x;
    int row = idx >> 8;
    int c4  = idx & 255;
    float4 v = reinterpret_cast<const float4*>(emb + (size_t)tgt[row] * ND)[c4];
    v.x *= 32.f; v.y *= 32.f; v.z *= 32.f; v.w *= 32.f;
    reinterpret_cast<float4*>(x)[idx] = v;
}

// ---------------- split-K reduce: out = relu(alpha*(P0+P1+bias)) ----------------
__global__ __launch_bounds__(256) void reduce2_kernel(
    float* __restrict__ out, const float* __restrict__ P,
    const float* __restrict__ bias, int N, int total4, float alpha, int relu)
{
    int idx = blockIdx.x * 256 + threadIdx.x;
    if (idx >= total4) return;
    const float4* P0 = reinterpret_cast<const float4*>(P);
    const float4* P1 = P0 + total4;
    float4 a = P0[idx], b = P1[idx];
    int col = (idx << 2) & (N - 1);          // N is a power of two here
    float4 bz = *reinterpret_cast<const float4*>(bias + col);
    float4 o;
    o.x = (a.x + b.x + bz.x) * alpha;
    o.y = (a.y + b.y + bz.y) * alpha;
    o.z = (a.z + b.z + bz.z) * alpha;
    o.w = (a.w + b.w + bz.w) * alpha;
    if (relu) {
        o.x = fmaxf(o.x, 0.f); o.y = fmaxf(o.y, 0.f);
        o.z = fmaxf(o.z, 0.f); o.w = fmaxf(o.w, 0.f);
    }
    reinterpret_cast<float4*>(out)[idx] = o;
}

// ---------------- split-bf16 tensor-core GEMM (mma.sync) ----------------
// C[M,N] (+z-slice) = alpha*((Ahi+Alo)[M,K]@(Bhi+Blo)[N,K]^T + bias), opt relu.
// CTA tile 128x128, k-tile 32, 8 warps (2x4), warp 64x32, 3-stage pipeline.
// gridDim.z = split-K count; slice z covers k in [z*K, (z+1)*K) of row stride ldk
// and writes C + z*M*N.
#define STG 32768
#define TOFF 8192
#define GEMM_SMEM (3*STG)

__device__ __forceinline__ void ld_tile_async(
    uint32_t sbase, const __nv_bfloat16* __restrict__ g,
    int ldk, int row0, int k0, int rmax, int tid)
{
    #pragma unroll
    for (int it = 0; it < 2; it++) {
        int qq = tid + it * 256;
        int r = qq >> 2, c = qq & 3;
        uint32_t dst = sbase + r * 64 + ((c ^ ((r >> 1) & 3)) << 4);
        int rr = (r < rmax) ? r : 0;
        const __nv_bfloat16* src = g + (size_t)(row0 + rr) * ldk + k0 + c * 8;
        int sz = (r < rmax) ? 16 : 0;
        CP_ASYNC16(dst, src, sz);
    }
}

__device__ __forceinline__ void ld_stage(
    uint32_t sbase, const __nv_bfloat16* Ah, const __nv_bfloat16* Al,
    const __nv_bfloat16* Bh, const __nv_bfloat16* Bl,
    int ldk, int m0, int n0, int k0, int bn, int tid)
{
    ld_tile_async(sbase + 0*TOFF, Ah, ldk, m0, k0, 128, tid);
    ld_tile_async(sbase + 1*TOFF, Al, ldk, m0, k0, 128, tid);
    ld_tile_async(sbase + 2*TOFF, Bh, ldk, n0, k0, bn, tid);
    ld_tile_async(sbase + 3*TOFF, Bl, ldk, n0, k0, bn, tid);
}

__global__ __launch_bounds__(256, 2) void gemm_tc(
    float* __restrict__ C,
    const __nv_bfloat16* __restrict__ Ah, const __nv_bfloat16* __restrict__ Al,
    const __nv_bfloat16* __restrict__ Bh, const __nv_bfloat16* __restrict__ Bl,
    const float* __restrict__ bias, int M, int N, int K, int ldk,
    float alpha, int relu)
{
    extern __shared__ char sm[];
    uint32_t smb = smem_u32(sm);
    int tid = threadIdx.x;
    int wid = tid >> 5;
    int lane = tid & 31;
    int wm = wid & 1;          // 2 warps along M
    int wn = wid >> 1;         // 4 warps along N
    int m0 = blockIdx.y * 128;
    int n0 = blockIdx.x * 128;
    int kbase = blockIdx.z * K;
    C += (size_t)blockIdx.z * M * N;
    int NT = K >> 5;
    int bn = N - n0; if (bn > 128) bn = 128;

    // prologue: stages 0,1 into slots 0,1
    ld_stage(smb, Ah, Al, Bh, Bl, ldk, m0, n0, kbase, bn, tid);
    CP_COMMIT();
    if (NT > 1) {
        ld_stage(smb + STG, Ah, Al, Bh, Bl, ldk, m0, n0, kbase + 32, bn, tid);
        CP_COMMIT();
    }

    float acc[4][4][4];
    #pragma unroll
    for (int i = 0; i < 4; i++)
        #pragma unroll
        for (int j = 0; j < 4; j++)
            #pragma unroll
            for (int e = 0; e < 4; e++) acc[i][j][e] = 0.f;

    int slot = 0;       // slot of k-tile kt
    int pslot = 2;      // slot where k-tile kt+2 goes
    for (int kt = 0; kt < NT; kt++) {
        if (kt + 1 < NT) { CP_WAIT1(); } else { CP_WAIT0(); }
        __syncthreads();

        // issue loads for kt+2 into the slot freed by iteration kt-1
        if (kt + 2 < NT) {
            ld_stage(smb + pslot * STG, Ah, Al, Bh, Bl, ldk, m0, n0,
                     kbase + ((kt + 2) << 5), bn, tid);
            CP_COMMIT();
        }

        uint32_t sA = smb + slot * STG;
        uint32_t sB = sA + 2*TOFF;

        #pragma unroll
        for (int ks = 0; ks < 2; ks++) {
            uint32_t ah[4][4], al[4][4], bh[4][2], bl[4][2];
            #pragma unroll
            for (int mf = 0; mf < 4; mf++) {
                int row = wm * 64 + mf * 16 + (lane & 15);
                int cc = ks * 2 + (lane >> 4);
                uint32_t ad = sA + row * 64 + (((cc ^ ((row >> 1) & 3))) << 4);
                LDSM4(ah[mf], ad);
                LDSM4(al[mf], ad + TOFF);
            }
            #pragma unroll
            for (int nf = 0; nf < 4; nf++) {
                int rn = wn * 32 + nf * 8 + (lane & 7);
                int cc = ks * 2 + ((lane >> 3) & 1);
                uint32_t bd = sB + rn * 64 + (((cc ^ ((rn >> 1) & 3))) << 4);
                LDSM2(bh[nf], bd);
                LDSM2(bl[nf], bd + TOFF);
            }
            // term-major: 16 independent MMAs per term
            #pragma unroll
            for (int mf = 0; mf < 4; mf++)
                #pragma unroll
                for (int nf = 0; nf < 4; nf++)
                    MMA16816(acc[mf][nf], ah[mf], bh[nf]);
            #pragma unroll
            for (int mf = 0; mf < 4; mf++)
                #pragma unroll
                for (int nf = 0; nf < 4; nf++)
                    MMA16816(acc[mf][nf], ah[mf], bl[nf]);
            #pragma unroll
            for (int mf = 0; mf < 4; mf++)
                #pragma unroll
                for (int nf = 0; nf < 4; nf++)
                    MMA16816(acc[mf][nf], al[mf], bh[nf]);
        }
        slot = (slot == 2) ? 0 : slot + 1;
        pslot = (pslot == 2) ? 0 : pslot + 1;
    }

    // epilogue
    bool fast = ((N & 1) == 0) && (n0 + 128 <= N);
    #pragma unroll
    for (int mf = 0; mf < 4; mf++) {
        int r0 = m0 + wm * 64 + mf * 16 + (lane >> 2);
        #pragma unroll
        for (int half = 0; half < 2; half++) {
            int row = r0 + half * 8;
            float* crow = C + (size_t)row * N;
            #pragma unroll
            for (int nf = 0; nf < 4; nf++) {
                int col = n0 + wn * 32 + nf * 8 + (lane & 3) * 2;
                float v0 = acc[mf][nf][half * 2 + 0];
                float v1 = acc[mf][nf][half * 2 + 1];
                if (bias) { v0 += bias[col]; v1 += __ldg(&bias[col + 1]); }
                v0 *= alpha; v1 *= alpha;
                if (relu) { v0 = fmaxf(v0, 0.f); v1 = fmaxf(v1, 0.f); }
                if (fast) {
                    *reinterpret_cast<float2*>(crow + col) = make_float2(v0, v1);
                } else {
                    if (col < N)     crow[col] = v0;
                    if (col + 1 < N) crow[col + 1] = v1;
                }
            }
        }
    }
}

// ---------------- fused attention (flash-style, exact softmax semantics) ----------------
#define QT 128
#define KT 64
#define LDQ 68

__global__ __launch_bounds__(128, 2) void attn_kernel(
    float* __restrict__ out, const float* __restrict__ q, const float* __restrict__ k,
    const float* __restrict__ v, const float* __restrict__ qr, const int* __restrict__ tgt)
{
    extern __shared__ float smf[];
    float* qs = smf;
    float* ks = qs + QT*LDQ;
    float* vs = ks + KT*LDQ;
    float* ps = vs + KT*LDQ;
    int*   pf = (int*)(ps + QT*LDQ);

    int b = blockIdx.z, h = blockIdx.y;
    int tid = threadIdx.x;
    int i0 = blockIdx.x * QT;
    int i  = i0 + tid;

    for (int t = tid; t < QT*NDH/4; t += 128) {
        int r  = t >> 4;
        int c4 = (t & 15) << 2;
        float4 va = *reinterpret_cast<const float4*>(
            &q[((size_t)(b*NS + i0 + r))*ND + h*NDH + c4]);
        *reinterpret_cast<float4*>(&qs[r*LDQ + c4]) = va;
    }

    float o[NDH];
    #pragma unroll
    for (int d = 0; d < NDH; d++) o[d] = 0.f;
    float m = -1e30f, l = 0.f;
    const float* qrrow = qr + ((size_t)((b*NS + i)*NH + h)) * NR + (1023 - i);

    // Causal tile skipping (bit-exact when key 0 is unmasked; see R4 notes).
    int jend = (tgt[b*NS] == 0) ? NS : (i0 + QT);

    for (int j0 = 0; j0 < jend; j0 += KT) {
        __syncthreads();
        for (int t = tid; t < KT*NDH/4; t += 128) {
            int r  = t >> 4;
            int c4 = (t & 15) << 2;
            size_t g = ((size_t)(b*NS + j0 + r))*ND + h*NDH + c4;
            *reinterpret_cast<float4*>(&ks[r*LDQ + c4]) =
                *reinterpret_cast<const float4*>(&k[g]);
            *reinterpret_cast<float4*>(&vs[r*LDQ + c4]) =
                *reinterpret_cast<const float4*>(&v[g]);
        }
        if (tid < KT) pf[tid] = (tgt[b*NS + j0 + tid] == 0) ? 1 : 0;
        __syncthreads();

        float s[KT];
        #pragma unroll
        for (int j = 0; j < KT; j++) s[j] = 0.f;
        #pragma unroll 1
        for (int d = 0; d < NDH; d += 4) {
            float4 qd = *reinterpret_cast<const float4*>(&qs[tid*LDQ + d]);
            #pragma unroll
            for (int j = 0; j < KT; j++) {
                float4 kj = *reinterpret_cast<const float4*>(&ks[j*LDQ + d]);
                s[j] += qd.x*kj.x + qd.y*kj.y + qd.z*kj.z + qd.w*kj.w;
            }
        }
        float mt = m;
        #pragma unroll
        for (int j = 0; j < KT; j++) {
            int jj = j0 + j;
            float val = s[j] + qrrow[jj];
            if (jj > i || pf[j]) val = -1e9f;
            s[j] = val;
            mt = fmaxf(mt, val);
        }
        float corr = __expf(m - mt);
        m = mt;
        l *= corr;
        #pragma unroll
        for (int d = 0; d < NDH; d++) o[d] *= corr;
        #pragma unroll
        for (int j = 0; j < KT; j += 4) {
            float4 pv;
            pv.x = __expf(s[j]   - m);
            pv.y = __expf(s[j+1] - m);
            pv.z = __expf(s[j+2] - m);
            pv.w = __expf(s[j+3] - m);
            l += pv.x + pv.y + pv.z + pv.w;
            *reinterpret_cast<float4*>(&ps[tid*LDQ + j]) = pv;
        }
        #pragma unroll 1
        for (int j = 0; j < KT; j++) {
            float p = ps[tid*LDQ + j];
            #pragma unroll
            for (int d = 0; d < NDH; d += 4) {
                float4 vj = *reinterpret_cast<const float4*>(&vs[j*LDQ + d]);
                o[d]   += p*vj.x;
                o[d+1] += p*vj.y;
                o[d+2] += p*vj.z;
                o[d+3] += p*vj.w;
            }
        }
    }
    float inv = 1.f / l;
    #pragma unroll
    for (int d = 0; d < NDH; d += 4) {
        float4 w;
        w.x = o[d]*inv; w.y = o[d+1]*inv; w.z = o[d+2]*inv; w.w = o[d+3]*inv;
        *reinterpret_cast<float4*>(&out[((size_t)(b*NS + i))*ND + h*NDH + d]) = w;
    }
}

// ---------------- residual add + LayerNorm (in place on x) ----------------
__global__ __launch_bounds__(256) void add_ln_kernel(
    float* __restrict__ x, const float* __restrict__ y,
    const float* __restrict__ gw, const float* __restrict__ bw)
{
    __shared__ float buf[ND];
    __shared__ float red[33];
    int row = blockIdx.x;
    int tid = threadIdx.x;
    size_t base = (size_t)row * ND;

    float s = 0.f;
    for (int d = tid; d < ND; d += 256) {
        float t = x[base + d] + y[base + d];
        buf[d] = t;
        s += t;
    }
    #pragma unroll
    for (int off = 16; off; off >>= 1) s += __shfl_xor_sync(0xffffffffu, s, off);
    if ((tid & 31) == 0) red[tid >> 5] = s;
    __syncthreads();
    if (tid < 32) {
        float v2 = (tid < 8) ? red[tid] : 0.f;
        #pragma unroll
        for (int off = 4; off; off >>= 1) v2 += __shfl_xor_sync(0xffffffffu, v2, off);
        if (tid == 0) red[32] = v2;
    }
    __syncthreads();
    float mean = red[32] * (1.f/ND);

    float sv = 0.f;
    for (int d = tid; d < ND; d += 256) {
        float t = buf[d] - mean;
        sv += t*t;
    }
    #pragma unroll
    for (int off = 16; off; off >>= 1) sv += __shfl_xor_sync(0xffffffffu, sv, off);
    __syncthreads();
    if ((tid & 31) == 0) red[tid >> 5] = sv;
    __syncthreads();
    if (tid < 32) {
        float v2 = (tid < 8) ? red[tid] : 0.f;
        #pragma unroll
        for (int off = 4; off; off >>= 1) v2 += __shfl_xor_sync(0xffffffffu, v2, off);
        if (tid == 0) red[32] = v2;
    }
    __syncthreads();
    float inv = rsqrtf(red[32] * (1.f/ND) + 1e-5f);
    for (int d = tid; d < ND; d += 256)
        x[base + d] = (buf[d] - mean) * inv * gw[d] + bw[d];
}

// ---------------- host orchestration ----------------
static inline void split(const float* src, __nv_bfloat16* hi, __nv_bfloat16* lo, size_t n) {
    int n4 = (int)(n / 4);
    split_kernel<<<(n4 + 255) / 256, 256>>>(
        reinterpret_cast<const float4*>(src), hi, lo, n4);
}

extern "C" void kernel_launch(void* const* d_in, const int* in_sizes, int n_in,
                              void* d_out, int out_size)
{
    (void)in_sizes; (void)n_in; (void)out_size;
    const int*   tgt = (const int*)d_in[0];
    const float* emb = (const float*)d_in[1];
    const float* Wq  = (const float*)d_in[2];
    const float* bq  = (const float*)d_in[3];
    const float* Wk  = (const float*)d_in[4];
    const float* bk  = (const float*)d_in[5];
    const float* Wv  = (const float*)d_in[6];
    const float* bv  = (const float*)d_in[7];
    const float* Wo  = (const float*)d_in[8];
    const float* bo  = (const float*)d_in[9];
    const float* rel = (const float*)d_in[10];
    const float* W1  = (const float*)d_in[11];
    const float* b1  = (const float*)d_in[12];
    const float* W2  = (const float*)d_in[13];
    const float* b2  = (const float*)d_in[14];
    const float* g1  = (const float*)d_in[15];
    const float* be1 = (const float*)d_in[16];
    const float* g2  = (const float*)d_in[17];
    const float* be2 = (const float*)d_in[18];
    const float* Wf  = (const float*)d_in[19];
    const float* bf  = (const float*)d_in[20];
    float* logits = (float*)d_out;

    float *x_, *q_, *k_, *v_, *o_, *t_, *h_, *p_, *qr_;
    __nv_bfloat16 *Ah, *Al, *Bh, *Bl;
    cudaGetSymbolAddress((void**)&x_,  g_x);
    cudaGetSymbolAddress((void**)&q_,  g_q);
    cudaGetSymbolAddress((void**)&k_,  g_k);
    cudaGetSymbolAddress((void**)&v_,  g_v);
    cudaGetSymbolAddress((void**)&o_,  g_o);
    cudaGetSymbolAddress((void**)&t_,  g_t);
    cudaGetSymbolAddress((void**)&h_,  g_h);
    cudaGetSymbolAddress((void**)&p_,  g_p);
    cudaGetSymbolAddress((void**)&qr_, g_qr);
    cudaGetSymbolAddress((void**)&Ah,  g_Ah);
    cudaGetSymbolAddress((void**)&Al,  g_Al);
    cudaGetSymbolAddress((void**)&Bh,  g_Bh);
    cudaGetSymbolAddress((void**)&Bl,  g_Bl);

    int attn_smem = (QT*LDQ + KT*LDQ + KT*LDQ + QT*LDQ)*(int)sizeof(float) + KT*(int)sizeof(int);
    cudaFuncSetAttribute(attn_kernel, cudaFuncAttributeMaxDynamicSharedMemorySize, attn_smem);
    cudaFuncSetAttribute(gemm_tc, cudaFuncAttributeMaxDynamicSharedMemorySize, GEMM_SMEM);

    embed_kernel<<<NROWS*ND/4/256, 256>>>(tgt, emb, x_);

    const int RED4 = NROWS*ND/4;            // reduce elements (float4)
    const dim3 gRED((RED4 + 255)/256);

    for (int l = 0; l < NL; l++) {
        const size_t WDD = (size_t)ND*ND;
        // q/k/v projections: split-K=2 (K=512 each half, ldk=1024)
        split(x_, Ah, Al, (size_t)NROWS*ND);
        split(Wq + l*WDD, Bh, Bl, WDD);
        gemm_tc<<<dim3(ND/128, NROWS/128, 2), 256, GEMM_SMEM>>>(
            p_, Ah, Al, Bh, Bl, nullptr, NROWS, ND, 512, ND, 1.f, 0);
        reduce2_kernel<<<gRED, 256>>>(q_, p_, bq + l*ND, ND, RED4, 0.125f, 0);
        split(Wk + l*WDD, Bh, Bl, WDD);
        gemm_tc<<<dim3(ND/128, NROWS/128, 2), 256, GEMM_SMEM>>>(
            p_, Ah, Al, Bh, Bl, nullptr, NROWS, ND, 512, ND, 1.f, 0);
        reduce2_kernel<<<gRED, 256>>>(k_, p_, bk + l*ND, ND, RED4, 1.f, 0);
        split(Wv + l*WDD, Bh, Bl, WDD);
        gemm_tc<<<dim3(ND/128, NROWS/128, 2), 256, GEMM_SMEM>>>(
            p_, Ah, Al, Bh, Bl, nullptr, NROWS, ND, 512, ND, 1.f, 0);
        reduce2_kernel<<<gRED, 256>>>(v_, p_, bv + l*ND, ND, RED4, 1.f, 0);

        // QR[bsh, r] = q . rel^T : M=32768, N=2047, K=64 (grid 4096, no split)
        split(q_, Ah, Al, (size_t)NROWS*ND);
        split(rel + (size_t)l*NR*NDH, Bh, Bl, (size_t)NR*NDH);
        gemm_tc<<<dim3((NR + 127)/128, NROWS*NH/128), 256, GEMM_SMEM>>>(
            qr_, Ah, Al, Bh, Bl, (const float*)nullptr, NROWS*NH, NR, NDH, NDH, 1.f, 0);

        attn_kernel<<<dim3(NS/QT, NH, NB), 128, attn_smem>>>(o_, q_, k_, v_, qr_, tgt);

        // output projection (split-K=2) + LN
        split(o_, Ah, Al, (size_t)NROWS*ND);
        split(Wo + l*WDD, Bh, Bl, WDD);
        gemm_tc<<<dim3(ND/128, NROWS/128, 2), 256, GEMM_SMEM>>>(
            p_, Ah, Al, Bh, Bl, nullptr, NROWS, ND, 512, ND, 1.f, 0);
        reduce2_kernel<<<gRED, 256>>>(t_, p_, bo + l*ND, ND, RED4, 1.f, 0);
        add_ln_kernel<<<NROWS, 256>>>(x_, t_, g1 + l*ND, be1 + l*ND);

        // FFN1 (grid 512, no split)
        split(x_, Ah, Al, (size_t)NROWS*ND);
        split(W1 + (size_t)l*NDFF*ND, Bh, Bl, (size_t)NDFF*ND);
        gemm_tc<<<dim3(NDFF/128, NROWS/128), 256, GEMM_SMEM>>>(
            h_, Ah, Al, Bh, Bl, b1 + l*NDFF, NROWS, NDFF, ND, ND, 1.f, 1);
        // FFN2 (K=4096 -> split-K=2 of 2048)
        split(h_, Ah, Al, (size_t)NROWS*NDFF);
        split(W2 + (size_t)l*ND*NDFF, Bh, Bl, (size_t)ND*NDFF);
        gemm_tc<<<dim3(ND/128, NROWS/128, 2), 256, GEMM_SMEM>>>(
            p_, Ah, Al, Bh, Bl, nullptr, NROWS, ND, 2048, NDFF, 1.f, 0);
        reduce2_kernel<<<gRED, 256>>>(t_, p_, b2 + l*ND, ND, RED4, 1.f, 0);
        add_ln_kernel<<<NROWS, 256>>>(x_, t_, g2 + l*ND, be2 + l*ND);
    }

    // final logits: M=2048, N=32000, K=1024 (grid 4000, no split)
    split(x_, Ah, Al, (size_t)NROWS*ND);
    split(Wf, Bh, Bl, (size_t)NV*ND);
    gemm_tc<<<dim3(NV/128, NROWS/128), 256, GEMM_SMEM>>>(
        logits, Ah, Al, Bh, Bl, bf, NROWS, NV, ND, ND, 1.f, 0);
}